// round 2
// baseline (speedup 1.0000x reference)
#include <cuda_runtime.h>

// ---------------------------------------------------------------------------
// CaT: 4-layer DAG-masked transformer, fp32, FFMA2 (fma.rn.f32x2) GEMM core.
// B=16, N=512, D=256, H=8, HS=64, FF=1024, L=4.
// Row index r = b*512 + n  (BN = 8192 rows).
// K/Q/V stored "n-major": buf[n*8192 + b*512 + h*64 + hs]  (512 x 8192)
// so A @ Q / A @ V is one batched GEMM with the shared (512x512) mask A.
// ---------------------------------------------------------------------------

#define DI __device__ __forceinline__

static DI float swishf(float x) { return x / (1.f + __expf(-x)); }

static const long long SS = 512LL * 8192LL;    // 4194304

// ------------------------- static device scratch ---------------------------
__device__ float g_Wpack[4 * 256 * 1536];        // [l][d][(t,h,hs)]
__device__ float g_Bias [4 * 1536];
__device__ unsigned char g_Amask[2 * 512 * 512]; // [v][i*512+j]
__device__ float g_KQV[3 * 512 * 8192];          // K | Q | V   (n-major)
__device__ float g_AQV[2 * 512 * 8192];          // AQ | AV     (n-major)
__device__ float g_Tb[33554432];                 // 128 * 512 * 512 scores
__device__ float g_Ob[8192 * 512];
__device__ float g_Mha[8192 * 256];
__device__ float g_Ff [8192 * 1024];
__device__ float g_Xb [8192 * 256];

// ------------------------------ prep kernels -------------------------------
__global__ void pack_w_k(const float* __restrict__ Wk, const float* __restrict__ Wq,
                         const float* __restrict__ Wv, const float* __restrict__ bk,
                         const float* __restrict__ bq, const float* __restrict__ bv) {
    int idx = blockIdx.x * 256 + threadIdx.x;
    if (idx < 4 * 256 * 1536) {
        int l = idx / (256 * 1536);
        int rem = idx - l * (256 * 1536);
        int d = rem / 1536;
        int c = rem - d * 1536;
        int t = c >> 9, h = (c >> 6) & 7, hs = c & 63;
        const float* W = (t == 0) ? Wk : (t == 1) ? Wq : Wv;
        g_Wpack[idx] = W[(((size_t)(l * 8 + h)) * 256 + d) * 64 + hs];
    }
    if (idx < 4 * 1536) {
        int l = idx / 1536;
        int c = idx - l * 1536;
        int t = c >> 9, h = (c >> 6) & 7, hs = c & 63;
        const float* bb = (t == 0) ? bk : (t == 1) ? bq : bv;
        g_Bias[idx] = bb[(l * 8 + h) * 64 + hs];
    }
}

__global__ void mask_k(const int* __restrict__ dag) {
    int idx = blockIdx.x * 256 + threadIdx.x;       // < 524288
    int v = idx >> 18;
    int rem = idx & 262143;
    int i = rem >> 9;
    int j = rem & 511;
    g_Amask[idx] = (unsigned char)((dag[j * 512 + i] != 0 || (v && i == j)) ? 1 : 0);
}

// ------------------------------- GEMM core ---------------------------------
struct GemmParams {
    const void*  A = nullptr;
    const float* B = nullptr;
    float*       C = nullptr;
    const float* bias = nullptr;
    const float* res  = nullptr;
    const unsigned char* mask = nullptr;
    float* dst0 = nullptr;
    int K = 0, lda = 0, ldb = 0, ldc = 0;
    long long sAz = 0, sBz = 0, sCz = 0;
};

// MODE: 0 plain, 1 QKV scatter+swish, 2 scale+mask, 3 PV(+AV residual scatter),
//       4 bias+swish, 5 bias+residual, 6 bias
template <int BN, bool TRANSB, bool AU8, int MODE>
__global__ __launch_bounds__(256) void gemm_k(GemmParams p) {
    constexpr int BM = 128, BK = 8;
    constexpr int CB = BN / 64;
    __shared__ __align__(16) float As2[BK][2 * BM];   // duplicated A tile
    __shared__ __align__(16) float Bs[BK][BN];

    const int t  = threadIdx.x;
    const int bx = blockIdx.x, by = blockIdx.y, bz = blockIdx.z;
    const int tx = t & 15, ty = t >> 4;

    const float* B = p.B + (size_t)bz * p.sBz;
    float*       C = p.C + (size_t)bz * p.sCz;
    const unsigned char* A8 = nullptr;
    const float*         Af = nullptr;
    if (AU8) A8 = (const unsigned char*)p.A + (size_t)bz * p.sAz + (size_t)by * BM * p.lda;
    else     Af = (const float*)p.A + (size_t)bz * p.sAz + (size_t)by * BM * p.lda;

    unsigned long long acc[2][CB][4][2];
#pragma unroll
    for (int rb = 0; rb < 2; rb++)
#pragma unroll
        for (int cb = 0; cb < CB; cb++)
#pragma unroll
            for (int i = 0; i < 4; i++) {
                acc[rb][cb][i][0] = 0ull; acc[rb][cb][i][1] = 0ull;
            }

    const int ar = t >> 1, ak = (t & 1) << 2;
    int b_r, b_c;
    if (TRANSB)        { b_r = t >> 1; b_c = (t & 1) << 2; }
    else if (BN == 128){ b_r = t >> 5; b_c = (t & 31) << 2; }
    else               { b_r = t >> 4; b_c = (t & 15) << 2; }

    const unsigned sA = (unsigned)__cvta_generic_to_shared(&As2[0][0]);
    const unsigned sB = (unsigned)__cvta_generic_to_shared(&Bs[0][0]);

    float4 av, bv;
    // ---- prefetch tile 0 ----
    {
        if (AU8) {
            unsigned w = *(const unsigned*)(A8 + (size_t)ar * p.lda + ak);
            av = make_float4((float)(w & 255u), (float)((w >> 8) & 255u),
                             (float)((w >> 16) & 255u), (float)(w >> 24));
        } else av = *(const float4*)(Af + (size_t)ar * p.lda + ak);
        if (TRANSB)
            bv = *(const float4*)(B + (size_t)(bx * BN + b_r) * p.ldb + b_c);
        else if (BN == 128 || t < 128)
            bv = *(const float4*)(B + (size_t)b_r * p.ldb + bx * BN + b_c);
    }

    for (int k0 = 0; k0 < p.K; k0 += BK) {
        // ---- store staged tile to smem ----
        {
            float va[4] = {av.x, av.y, av.z, av.w};
#pragma unroll
            for (int q = 0; q < 4; q++) {
                As2[ak + q][2 * ar]     = va[q];
                As2[ak + q][2 * ar + 1] = va[q];
            }
            if (TRANSB) {
                float vb[4] = {bv.x, bv.y, bv.z, bv.w};
#pragma unroll
                for (int q = 0; q < 4; q++) Bs[b_c + q][b_r] = vb[q];
            } else if (BN == 128 || t < 128) {
                *(float4*)&Bs[b_r][b_c] = bv;
            }
        }
        __syncthreads();
        // ---- prefetch next tile ----
        if (k0 + BK < p.K) {
            const int kn = k0 + BK;
            if (AU8) {
                unsigned w = *(const unsigned*)(A8 + (size_t)ar * p.lda + kn + ak);
                av = make_float4((float)(w & 255u), (float)((w >> 8) & 255u),
                                 (float)((w >> 16) & 255u), (float)(w >> 24));
            } else av = *(const float4*)(Af + (size_t)ar * p.lda + kn + ak);
            if (TRANSB)
                bv = *(const float4*)(B + (size_t)(bx * BN + b_r) * p.ldb + kn + b_c);
            else if (BN == 128 || t < 128)
                bv = *(const float4*)(B + (size_t)(kn + b_r) * p.ldb + bx * BN + b_c);
        }
        // ---- compute ----
#pragma unroll
        for (int kk = 0; kk < BK; kk++) {
            unsigned long long a[2][4], b[CB][2];
#pragma unroll
            for (int rb = 0; rb < 2; rb++) {
                const unsigned ao = sA + (unsigned)(kk * (2 * BM * 4) + (rb * 64 + ty * 4) * 8);
                asm volatile("ld.shared.v2.u64 {%0,%1}, [%2];"
                             : "=l"(a[rb][0]), "=l"(a[rb][1]) : "r"(ao));
                asm volatile("ld.shared.v2.u64 {%0,%1}, [%2];"
                             : "=l"(a[rb][2]), "=l"(a[rb][3]) : "r"(ao + 16));
            }
#pragma unroll
            for (int cb = 0; cb < CB; cb++) {
                const unsigned bo = sB + (unsigned)(kk * (BN * 4) + (cb * 64 + tx * 4) * 4);
                asm volatile("ld.shared.v2.u64 {%0,%1}, [%2];"
                             : "=l"(b[cb][0]), "=l"(b[cb][1]) : "r"(bo));
            }
#pragma unroll
            for (int rb = 0; rb < 2; rb++)
#pragma unroll
                for (int cb = 0; cb < CB; cb++)
#pragma unroll
                    for (int i = 0; i < 4; i++) {
                        asm("fma.rn.f32x2 %0, %1, %2, %0;"
                            : "+l"(acc[rb][cb][i][0]) : "l"(a[rb][i]), "l"(b[cb][0]));
                        asm("fma.rn.f32x2 %0, %1, %2, %0;"
                            : "+l"(acc[rb][cb][i][1]) : "l"(a[rb][i]), "l"(b[cb][1]));
                    }
        }
        __syncthreads();
    }

    // ---- epilogue ----
#pragma unroll
    for (int rb = 0; rb < 2; rb++)
#pragma unroll
        for (int i = 0; i < 4; i++) {
            const int gm = by * BM + rb * 64 + ty * 4 + i;
#pragma unroll
            for (int cb = 0; cb < CB; cb++)
#pragma unroll
                for (int jp = 0; jp < 2; jp++) {
                    const unsigned long long u = acc[rb][cb][i][jp];
                    float vh[2];
                    vh[0] = __int_as_float((int)(unsigned)u);
                    vh[1] = __int_as_float((int)(u >> 32));
#pragma unroll
                    for (int h = 0; h < 2; h++) {
                        const int gn = bx * BN + cb * 64 + tx * 4 + jp * 2 + h;
                        float v = vh[h];
                        if (MODE == 0) {
                            C[(size_t)gm * p.ldc + gn] = v;
                        } else if (MODE == 1) {
                            v = swishf(v + p.bias[gn]);
                            const int tt = gn >> 9, hh = (gn >> 6) & 7, hs = gn & 63;
                            const int bb = gm >> 9, n = gm & 511;
                            p.dst0[(size_t)tt * SS + (size_t)n * 8192 + bb * 512 + hh * 64 + hs] = v;
                        } else if (MODE == 2) {
                            v = p.mask[gm * 512 + gn] ? v * 0.125f : -3.0e38f;
                            C[(size_t)gm * p.ldc + gn] = v;
                        } else if (MODE == 3) {
                            v += p.res[(size_t)gm * 8192 + bz * 64 + gn];
                            C[(size_t)((bz >> 3) * 512 + gm) * 512 + (bz & 7) * 64 + gn] = v;
                        } else if (MODE == 4) {
                            C[(size_t)gm * p.ldc + gn] = swishf(v + p.bias[gn]);
                        } else if (MODE == 5) {
                            C[(size_t)gm * p.ldc + gn] =
                                v + p.bias[gn] + p.res[(size_t)gm * p.ldc + gn];
                        } else {
                            C[(size_t)gm * p.ldc + gn] = v + p.bias[gn];
                        }
                    }
                }
        }
}

// ------------------------------- softmax -----------------------------------
__global__ void softmax_k(float* __restrict__ T) {
    int row  = blockIdx.x * 8 + (threadIdx.x >> 5);
    int lane = threadIdx.x & 31;
    float* r = T + (size_t)row * 512;
    float x[16];
    float m = -3.4e38f;
#pragma unroll
    for (int k = 0; k < 16; k++) { x[k] = r[k * 32 + lane]; m = fmaxf(m, x[k]); }
#pragma unroll
    for (int o = 16; o; o >>= 1) m = fmaxf(m, __shfl_xor_sync(0xffffffffu, m, o));
    if (m <= -1e37f) {
#pragma unroll
        for (int k = 0; k < 16; k++) r[k * 32 + lane] = 0.f;
        return;
    }
    float s = 0.f;
#pragma unroll
    for (int k = 0; k < 16; k++) { x[k] = __expf(x[k] - m); s += x[k]; }
#pragma unroll
    for (int o = 16; o; o >>= 1) s += __shfl_xor_sync(0xffffffffu, s, o);
    float inv = 1.f / s;
#pragma unroll
    for (int k = 0; k < 16; k++) r[k * 32 + lane] = x[k] * inv;
}

// ------------------------------ host driver --------------------------------
extern "C" void kernel_launch(void* const* d_in, const int* in_sizes, int n_in,
                              void* d_out, int out_size) {
    (void)in_sizes; (void)n_in; (void)out_size;
    const float* X   = (const float*)d_in[0];
    const int*   dag = (const int*)d_in[1];
    const float* Wk  = (const float*)d_in[2],  *bk  = (const float*)d_in[3];
    const float* Wq  = (const float*)d_in[4],  *bq  = (const float*)d_in[5];
    const float* Wv  = (const float*)d_in[6],  *bv  = (const float*)d_in[7];
    const float* Wp  = (const float*)d_in[8],  *bp  = (const float*)d_in[9];
    const float* W1  = (const float*)d_in[10], *b1  = (const float*)d_in[11];
    const float* W2  = (const float*)d_in[12], *b2  = (const float*)d_in[13];
    const float* Wlm = (const float*)d_in[14], *blm = (const float*)d_in[15];
    float* out = (float*)d_out;

    void* pv;
    cudaGetSymbolAddress(&pv, g_Wpack); float* Wpack = (float*)pv;
    cudaGetSymbolAddress(&pv, g_Bias);  float* Bias  = (float*)pv;
    cudaGetSymbolAddress(&pv, g_Amask); unsigned char* Amask = (unsigned char*)pv;
    cudaGetSymbolAddress(&pv, g_KQV);   float* KQV = (float*)pv;
    cudaGetSymbolAddress(&pv, g_AQV);   float* AQV = (float*)pv;
    cudaGetSymbolAddress(&pv, g_Tb);    float* Tb  = (float*)pv;
    cudaGetSymbolAddress(&pv, g_Ob);    float* Ob  = (float*)pv;
    cudaGetSymbolAddress(&pv, g_Mha);   float* Mha = (float*)pv;
    cudaGetSymbolAddress(&pv, g_Ff);    float* Ff  = (float*)pv;
    cudaGetSymbolAddress(&pv, g_Xb);    float* Xb  = (float*)pv;

    pack_w_k<<<6144, 256>>>(Wk, Wq, Wv, bk, bq, bv);
    mask_k<<<2048, 256>>>(dag);

    for (int l = 0; l < 4; l++) {
        const unsigned char* Am = Amask + (l ? 262144 : 0);
        {   // QKV projection + bias + swish, scattered to n-major K/Q/V
            GemmParams p; p.A = (l == 0) ? (const void*)X : (const void*)Xb; p.lda = 256;
            p.B = Wpack + (size_t)l * 256 * 1536; p.ldb = 1536;
            p.bias = Bias + l * 1536; p.dst0 = KQV; p.K = 256;
            gemm_k<128, false, false, 1><<<dim3(12, 64, 1), 256>>>(p);
        }
        {   // [AQ | AV] = A @ [Q | V]   batched over z = {Q, V}
            GemmParams p; p.A = Am; p.lda = 512;
            p.B = KQV + SS; p.ldb = 8192; p.sBz = SS;
            p.C = AQV; p.ldc = 8192; p.sCz = SS; p.K = 512;
            gemm_k<128, false, true, 0><<<dim3(64, 4, 2), 256>>>(p);
        }
        {   // scores T = (AQ Kt)/8, masked -> Tb  (batched over 128 bh)
            GemmParams p; p.A = AQV; p.lda = 8192; p.sAz = 64;
            p.B = KQV; p.ldb = 8192; p.sBz = 64;
            p.C = Tb; p.ldc = 512; p.sCz = 262144; p.mask = Am; p.K = 64;
            gemm_k<128, true, false, 2><<<dim3(4, 4, 128), 256>>>(p);
        }
        softmax_k<<<8192, 256>>>(Tb);
        {   // O = P @ V + AV, scattered to (b,n) x (h,hs)
            GemmParams p; p.A = Tb; p.lda = 512; p.sAz = 262144;
            p.B = KQV + 2 * SS; p.ldb = 8192; p.sBz = 64;
            p.C = Ob; p.res = AQV + SS; p.K = 512;
            gemm_k<64, false, false, 3><<<dim3(1, 4, 128), 256>>>(p);
        }
        {   // mha = swish(O @ Wp + bp)
            GemmParams p; p.A = Ob; p.lda = 512;
            p.B = Wp + (size_t)l * 512 * 256; p.ldb = 256; p.bias = bp + l * 256;
            p.C = Mha; p.ldc = 256; p.K = 512;
            gemm_k<64, false, false, 4><<<dim3(4, 64, 1), 256>>>(p);
        }
        {   // ff hidden = swish(mha @ W1 + b1)
            GemmParams p; p.A = Mha; p.lda = 256;
            p.B = W1 + (size_t)l * 256 * 1024; p.ldb = 1024; p.bias = b1 + l * 1024;
            p.C = Ff; p.ldc = 1024; p.K = 256;
            gemm_k<128, false, false, 4><<<dim3(8, 64, 1), 256>>>(p);
        }
        {   // X = ff @ W2 + b2 + mha
            GemmParams p; p.A = Ff; p.lda = 1024;
            p.B = W2 + (size_t)l * 1024 * 256; p.ldb = 256; p.bias = b2 + l * 256;
            p.res = Mha; p.C = Xb; p.ldc = 256; p.K = 1024;
            gemm_k<64, false, false, 5><<<dim3(4, 64, 1), 256>>>(p);
        }
    }
    {   // lm head
        GemmParams p; p.A = Xb; p.lda = 256; p.B = Wlm; p.ldb = 256;
        p.bias = blm; p.C = out; p.ldc = 256; p.K = 256;
        gemm_k<64, false, false, 6><<<dim3(4, 64, 1), 256>>>(p);
    }
}

// round 6
// speedup vs baseline: 2.2525x; 2.2525x over previous
#include <cuda_runtime.h>
#include <cstdint>

// ---------------------------------------------------------------------------
// CaT transformer on tf32 mma.sync tensor cores (portable sm_100 target).
// B=16, N=512, D=256, H=8, HS=64, FF=1024, L=4.
// Every GEMM is D = A @ B^T with A,B K-major (mma row.col).
// O = P@V + A@V == (P + A) @ V  (mask folded into probabilities by softmax).
// Fragments loaded with plain LDS per the documented m16n8k8 coordinates.
// ---------------------------------------------------------------------------

#define DI __device__ __forceinline__

static DI float swishf(float x) { return x / (1.f + __expf(-x)); }

// ------------------------- static device scratch ---------------------------
__device__ float g_Wqkvt[4 * 1536 * 256];   // [l][(t,h,hs)][d]
__device__ float g_Bqkv [4 * 1536];
__device__ float g_Wpt  [4 * 256 * 512];    // [l][n][k]
__device__ float g_W1t  [4 * 1024 * 256];
__device__ float g_W2t  [4 * 256 * 1024];
__device__ float g_Wlmt [256 * 256];
__device__ unsigned char g_Amask[2 * 512 * 512];
__device__ float g_KQV[3 * 512 * 8192];     // K[z][n][hs] | Qt[(z,hs)][n] | Vt[(z,hs)][n]
__device__ float g_AQ4[512 * 8192];         // [z][i][hs]
__device__ float g_Tb [128 * 512 * 512];    // scores / probs
__device__ float g_Ob [8192 * 512];
__device__ float g_Mha[8192 * 256];
__device__ float g_Ff [8192 * 1024];
__device__ float g_Xb [8192 * 256];

// ------------------------------ prep kernels -------------------------------
__global__ void pack_qkv_k(const float* __restrict__ Wk, const float* __restrict__ Wq,
                           const float* __restrict__ Wv, const float* __restrict__ bk,
                           const float* __restrict__ bq, const float* __restrict__ bv) {
    int idx = blockIdx.x * 256 + threadIdx.x;          // < 1572864
    int l = idx / 393216;                               // 1536*256 (NOT a power of 2)
    int rem = idx - l * 393216;
    int r = rem >> 8;
    int d = rem & 255;
    int t = r >> 9, h = (r >> 6) & 7, hs = r & 63;
    const float* W = (t == 0) ? Wk : (t == 1) ? Wq : Wv;
    g_Wqkvt[idx] = W[(((size_t)(l * 8 + h)) * 256 + d) * 64 + hs];
    if (idx < 4 * 1536) {
        int ll = idx / 1536;
        int c = idx - ll * 1536;
        int tt = c >> 9, hh = (c >> 6) & 7, hss = c & 63;
        const float* bb = (tt == 0) ? bk : (tt == 1) ? bq : bv;
        g_Bqkv[idx] = bb[(ll * 8 + hh) * 64 + hss];
    }
}

__global__ void pack_rest_k(const float* __restrict__ Wp, const float* __restrict__ W1,
                            const float* __restrict__ W2, const float* __restrict__ Wlm) {
    int idx = blockIdx.x * 256 + threadIdx.x;          // < 2686976
    if (idx < 524288) {                                 // Wpt [l][n(256)][k(512)]
        int l = idx >> 17, rem = idx & 131071;
        int n = rem >> 9, k = rem & 511;
        g_Wpt[idx] = Wp[((size_t)l * 512 + k) * 256 + n];
        return;
    }
    idx -= 524288;
    if (idx < 1048576) {                                // W1t [l][n(1024)][d(256)]
        int l = idx >> 18, rem = idx & 262143;
        int n = rem >> 8, d = rem & 255;
        g_W1t[idx] = W1[((size_t)l * 256 + d) * 1024 + n];
        return;
    }
    idx -= 1048576;
    if (idx < 1048576) {                                // W2t [l][n(256)][f(1024)]
        int l = idx >> 18, rem = idx & 262143;
        int n = rem >> 10, f = rem & 1023;
        g_W2t[idx] = W2[((size_t)l * 1024 + f) * 256 + n];
        return;
    }
    idx -= 1048576;
    if (idx < 65536) {                                  // Wlmt [n][d]
        int n = idx >> 8, d = idx & 255;
        g_Wlmt[idx] = Wlm[d * 256 + n];
    }
}

__global__ void mask_k(const int* __restrict__ dag) {
    int idx = blockIdx.x * 256 + threadIdx.x;          // < 524288
    int v = idx >> 18;
    int rem = idx & 262143;
    int i = rem >> 9;
    int j = rem & 511;
    g_Amask[idx] = (unsigned char)((dag[j * 512 + i] != 0 || (v && i == j)) ? 1 : 0);
}

// ------------------------------- GEMM core ---------------------------------
struct GP {
    const void*  A; const float* B; float* C;
    const float* bias; const float* res; const unsigned char* mask;
    float* dst0;
    int K, lda, ldb, ldc;
    long long sAz, sBz, sCz;
};

DI unsigned tf32_rn(float x) {
    unsigned r;
    asm("cvt.rn.tf32.f32 %0, %1;" : "=r"(r) : "f"(x));
    return r;
}

// MODE: 1 QKV scatter  2 score mask  3 AQ scatter  4 bias+swish
//       5 bias+residual  6 bias  7 PV scatter
template <int BN, bool AU8, int MODE>
__global__ __launch_bounds__(256) void gemm_tc(GP p) {
    constexpr int BM = 128, BK = 16, PITCH = 20;       // floats per smem row
    constexpr int WNW = (BN == 128) ? 4 : 2;           // warps along N
    constexpr int WM  = (BN == 128) ? 64 : 32;         // rows per warp
    constexpr int WN  = 32;                            // cols per warp
    constexpr int MT  = WM / 16, NT = WN / 8;
    constexpr int ALD = 2;                             // A float4 loads / thread
    constexpr int BLD = (BN * BK) / (4 * 256);         // B float4 loads / thread

    __shared__ __align__(16) float As[BM * PITCH];
    __shared__ __align__(16) float Bs[BN * PITCH];

    const int t = threadIdx.x, lane = t & 31, w = t >> 5;
    const int wm = w / WNW, wn = w % WNW;
    const int g = lane >> 2, cc = lane & 3;            // fragment coords
    const int bx = blockIdx.x, by = blockIdx.y, bz = blockIdx.z;

    const unsigned char* A8 = nullptr;
    const float* Af = nullptr;
    if (AU8) A8 = (const unsigned char*)p.A + (size_t)by * BM * p.lda;
    else     Af = (const float*)p.A + (size_t)bz * p.sAz + (size_t)by * BM * p.lda;
    const float* Bp = p.B + (size_t)bz * p.sBz + (size_t)bx * BN * p.ldb;
    float* C = p.C + (size_t)bz * p.sCz;

    const unsigned sA = (unsigned)__cvta_generic_to_shared(As);
    const unsigned sB = (unsigned)__cvta_generic_to_shared(Bs);

    float acc[MT][NT][4];
#pragma unroll
    for (int i = 0; i < MT; i++)
#pragma unroll
        for (int j = 0; j < NT; j++)
#pragma unroll
            for (int r = 0; r < 4; r++) acc[i][j][r] = 0.f;

    float4 avA[ALD], avB[BLD];

    auto loadG = [&](int k0) {
#pragma unroll
        for (int i = 0; i < ALD; i++) {
            const int idx = i * 256 + t;
            const int r = idx >> 2, c = (idx & 3) << 2;
            if (AU8) {
                uchar4 u = *(const uchar4*)(A8 + (size_t)r * p.lda + k0 + c);
                avA[i] = make_float4((float)u.x, (float)u.y, (float)u.z, (float)u.w);
            } else {
                avA[i] = *(const float4*)(Af + (size_t)r * p.lda + k0 + c);
            }
        }
#pragma unroll
        for (int i = 0; i < BLD; i++) {
            const int idx = i * 256 + t;
            const int r = idx >> 2, c = (idx & 3) << 2;
            avB[i] = *(const float4*)(Bp + (size_t)r * p.ldb + k0 + c);
        }
    };
    auto storeS = [&]() {
#pragma unroll
        for (int i = 0; i < ALD; i++) {
            const int idx = i * 256 + t;
            const int r = idx >> 2, c = (idx & 3) << 2;
            unsigned w0 = tf32_rn(avA[i].x), w1 = tf32_rn(avA[i].y);
            unsigned w2 = tf32_rn(avA[i].z), w3 = tf32_rn(avA[i].w);
            asm volatile("st.shared.v4.b32 [%0], {%1,%2,%3,%4};"
                         :: "r"(sA + (unsigned)((r * PITCH + c) * 4)),
                            "r"(w0), "r"(w1), "r"(w2), "r"(w3));
        }
#pragma unroll
        for (int i = 0; i < BLD; i++) {
            const int idx = i * 256 + t;
            const int r = idx >> 2, c = (idx & 3) << 2;
            unsigned w0 = tf32_rn(avB[i].x), w1 = tf32_rn(avB[i].y);
            unsigned w2 = tf32_rn(avB[i].z), w3 = tf32_rn(avB[i].w);
            asm volatile("st.shared.v4.b32 [%0], {%1,%2,%3,%4};"
                         :: "r"(sB + (unsigned)((r * PITCH + c) * 4)),
                            "r"(w0), "r"(w1), "r"(w2), "r"(w3));
        }
    };

    const int nch = p.K >> 4;
    loadG(0);
    for (int c = 0; c < nch; c++) {
        storeS();
        __syncthreads();
        if (c + 1 < nch) loadG((c + 1) << 4);
        // ---- compute on the smem tile: fragments via direct LDS ----
#pragma unroll
        for (int ks = 0; ks < 2; ks++) {
            const int kb = ks * 8;
            unsigned a[MT][4], b[NT][2];
#pragma unroll
            for (int i = 0; i < MT; i++) {
                const int r0 = (wm * WM + i * 16 + g) * PITCH + kb + cc;
                a[i][0] = __float_as_uint(As[r0]);
                a[i][1] = __float_as_uint(As[r0 + 8 * PITCH]);
                a[i][2] = __float_as_uint(As[r0 + 4]);
                a[i][3] = __float_as_uint(As[r0 + 8 * PITCH + 4]);
            }
#pragma unroll
            for (int j = 0; j < NT; j++) {
                const int r0 = (wn * WN + j * 8 + g) * PITCH + kb + cc;
                b[j][0] = __float_as_uint(Bs[r0]);
                b[j][1] = __float_as_uint(Bs[r0 + 4]);
            }
#pragma unroll
            for (int i = 0; i < MT; i++)
#pragma unroll
                for (int j = 0; j < NT; j++)
                    asm volatile(
                        "mma.sync.aligned.m16n8k8.row.col.f32.tf32.tf32.f32 "
                        "{%0,%1,%2,%3}, {%4,%5,%6,%7}, {%8,%9}, {%0,%1,%2,%3};"
                        : "+f"(acc[i][j][0]), "+f"(acc[i][j][1]),
                          "+f"(acc[i][j][2]), "+f"(acc[i][j][3])
                        : "r"(a[i][0]), "r"(a[i][1]), "r"(a[i][2]), "r"(a[i][3]),
                          "r"(b[j][0]), "r"(b[j][1]));
        }
        __syncthreads();
    }

    // ------------------------------ epilogue -------------------------------
#pragma unroll
    for (int i = 0; i < MT; i++)
#pragma unroll
        for (int j = 0; j < NT; j++)
#pragma unroll
            for (int r = 0; r < 4; r++) {
                const int gm = by * BM + wm * WM + i * 16 + ((r >> 1) << 3) + g;
                const int gn = bx * BN + wn * WN + j * 8 + (cc << 1) + (r & 1);
                float v = acc[i][j][r];
                if (MODE == 1) {
                    v = swishf(v + p.bias[gn]);
                    const int tt = gn >> 9, h = (gn >> 6) & 7, hs = gn & 63;
                    const int b = gm >> 9, n = gm & 511, z = b * 8 + h;
                    if (tt == 0)      p.dst0[(size_t)(z * 512 + n) * 64 + hs] = v;
                    else if (tt == 1) p.dst0[4194304u + (size_t)(z * 64 + hs) * 512 + n] = v;
                    else              p.dst0[8388608u + (size_t)(z * 64 + hs) * 512 + n] = v;
                } else if (MODE == 2) {
                    v = p.mask[gm * 512 + gn] ? v * 0.125f : -3.0e38f;
                    C[(size_t)gm * p.ldc + gn] = v;
                } else if (MODE == 3) {
                    p.C[(size_t)(gn >> 6) * 32768 + (size_t)gm * 64 + (gn & 63)] = v;
                } else if (MODE == 4) {
                    C[(size_t)gm * p.ldc + gn] = swishf(v + p.bias[gn]);
                } else if (MODE == 5) {
                    C[(size_t)gm * p.ldc + gn] = v + p.bias[gn] + p.res[(size_t)gm * p.ldc + gn];
                } else if (MODE == 6) {
                    C[(size_t)gm * p.ldc + gn] = v + p.bias[gn];
                } else {   // MODE 7: PV out -> Ob[(b,i)][(h,hs)]
                    p.C[(size_t)((bz >> 3) * 512 + gm) * 512 + (bz & 7) * 64 + gn] = v;
                }
            }
}

// ----------------------- softmax (+ mask fold-in) --------------------------
__global__ void softmax_k(float* __restrict__ T, const unsigned char* __restrict__ M) {
    const int row  = blockIdx.x * 8 + (threadIdx.x >> 5);   // 65536 rows
    const int lane = threadIdx.x & 31;
    const int i = row & 511;
    float* r = T + (size_t)row * 512;
    const unsigned char* mr = M + i * 512;
    float x[16];
    float m = -3.4e38f;
#pragma unroll
    for (int k = 0; k < 16; k++) { x[k] = r[k * 32 + lane]; m = fmaxf(m, x[k]); }
#pragma unroll
    for (int o = 16; o; o >>= 1) m = fmaxf(m, __shfl_xor_sync(0xffffffffu, m, o));
    if (m <= -1e37f) {
#pragma unroll
        for (int k = 0; k < 16; k++) r[k * 32 + lane] = 0.f;
        return;
    }
    float s = 0.f;
#pragma unroll
    for (int k = 0; k < 16; k++) { x[k] = __expf(x[k] - m); s += x[k]; }
#pragma unroll
    for (int o = 16; o; o >>= 1) s += __shfl_xor_sync(0xffffffffu, s, o);
    const float inv = 1.f / s;
#pragma unroll
    for (int k = 0; k < 16; k++)
        r[k * 32 + lane] = x[k] * inv + (float)mr[k * 32 + lane];   // P + A
}

// ------------------------------ host driver --------------------------------
extern "C" void kernel_launch(void* const* d_in, const int* in_sizes, int n_in,
                              void* d_out, int out_size) {
    (void)in_sizes; (void)n_in; (void)out_size;
    const float* X   = (const float*)d_in[0];
    const int*   dag = (const int*)d_in[1];
    const float* Wk  = (const float*)d_in[2],  *bk  = (const float*)d_in[3];
    const float* Wq  = (const float*)d_in[4],  *bq  = (const float*)d_in[5];
    const float* Wv  = (const float*)d_in[6],  *bv  = (const float*)d_in[7];
    const float* Wp  = (const float*)d_in[8],  *bp  = (const float*)d_in[9];
    const float* W1  = (const float*)d_in[10], *b1  = (const float*)d_in[11];
    const float* W2  = (const float*)d_in[12], *b2  = (const float*)d_in[13];
    const float* Wlm = (const float*)d_in[14], *blm = (const float*)d_in[15];
    float* out = (float*)d_out;

    void* pv;
    cudaGetSymbolAddress(&pv, g_Wqkvt); float* Wqkvt = (float*)pv;
    cudaGetSymbolAddress(&pv, g_Bqkv);  float* Bqkv  = (float*)pv;
    cudaGetSymbolAddress(&pv, g_Wpt);   float* Wpt   = (float*)pv;
    cudaGetSymbolAddress(&pv, g_W1t);   float* W1t   = (float*)pv;
    cudaGetSymbolAddress(&pv, g_W2t);   float* W2t   = (float*)pv;
    cudaGetSymbolAddress(&pv, g_Wlmt);  float* Wlmt  = (float*)pv;
    cudaGetSymbolAddress(&pv, g_Amask); unsigned char* Amask = (unsigned char*)pv;
    cudaGetSymbolAddress(&pv, g_KQV);   float* KQV = (float*)pv;
    cudaGetSymbolAddress(&pv, g_AQ4);   float* AQ4 = (float*)pv;
    cudaGetSymbolAddress(&pv, g_Tb);    float* Tb  = (float*)pv;
    cudaGetSymbolAddress(&pv, g_Ob);    float* Ob  = (float*)pv;
    cudaGetSymbolAddress(&pv, g_Mha);   float* Mha = (float*)pv;
    cudaGetSymbolAddress(&pv, g_Ff);    float* Ff  = (float*)pv;
    cudaGetSymbolAddress(&pv, g_Xb);    float* Xb  = (float*)pv;

    pack_qkv_k<<<6144, 256>>>(Wk, Wq, Wv, bk, bq, bv);
    pack_rest_k<<<10496, 256>>>(Wp, W1, W2, Wlm);
    mask_k<<<2048, 256>>>(dag);

    for (int l = 0; l < 4; l++) {
        const unsigned char* Am = Amask + (l ? 262144 : 0);
        {   // QKV: X @ Wqkvt^T -> scatter K/Qt/Vt (+bias+swish)
            GP p{}; p.A = (l == 0) ? (const void*)X : (const void*)Xb; p.lda = 256;
            p.B = Wqkvt + (size_t)l * 1536 * 256; p.ldb = 256;
            p.bias = Bqkv + l * 1536; p.dst0 = KQV; p.K = 256;
            gemm_tc<128, false, 1><<<dim3(12, 64, 1), 256>>>(p);
        }
        {   // AQ = mask @ Qt^T  -> AQ4[z][i][hs]
            GP p{}; p.A = Am; p.lda = 512;
            p.B = KQV + 4194304; p.ldb = 512;
            p.C = AQ4; p.K = 512;
            gemm_tc<128, true, 3><<<dim3(64, 4, 1), 256>>>(p);
        }
        {   // scores = (AQ4 @ K^T)/8, masked -> Tb   (z over 128 bh)
            GP p{}; p.A = AQ4; p.lda = 64; p.sAz = 32768;
            p.B = KQV; p.ldb = 64; p.sBz = 32768;
            p.C = Tb; p.ldc = 512; p.sCz = 262144; p.mask = Am; p.K = 64;
            gemm_tc<128, false, 2><<<dim3(4, 4, 128), 256>>>(p);
        }
        softmax_k<<<8192, 256>>>(Tb, Am);
        {   // O = (P+A) @ Vt^T -> Ob[(b,i)][(h,hs)]
            GP p{}; p.A = Tb; p.lda = 512; p.sAz = 262144;
            p.B = KQV + 2 * 4194304; p.ldb = 512; p.sBz = 32768;
            p.C = Ob; p.K = 512;
            gemm_tc<64, false, 7><<<dim3(1, 4, 128), 256>>>(p);
        }
        {   // mha = swish(Ob @ Wpt^T + bp)
            GP p{}; p.A = Ob; p.lda = 512;
            p.B = Wpt + (size_t)l * 256 * 512; p.ldb = 512;
            p.bias = bp + l * 256; p.C = Mha; p.ldc = 256; p.K = 512;
            gemm_tc<128, false, 4><<<dim3(2, 64, 1), 256>>>(p);
        }
        {   // ff = swish(mha @ W1t^T + b1)
            GP p{}; p.A = Mha; p.lda = 256;
            p.B = W1t + (size_t)l * 1024 * 256; p.ldb = 256;
            p.bias = b1 + l * 1024; p.C = Ff; p.ldc = 1024; p.K = 256;
            gemm_tc<128, false, 4><<<dim3(8, 64, 1), 256>>>(p);
        }
        {   // X = ff @ W2t^T + b2 + mha
            GP p{}; p.A = Ff; p.lda = 1024;
            p.B = W2t + (size_t)l * 256 * 1024; p.ldb = 1024;
            p.bias = b2 + l * 256; p.res = Mha; p.C = Xb; p.ldc = 256; p.K = 1024;
            gemm_tc<128, false, 5><<<dim3(2, 64, 1), 256>>>(p);
        }
    }
    {   // lm head
        GP p{}; p.A = Xb; p.lda = 256; p.B = Wlmt; p.ldb = 256;
        p.bias = blm; p.C = out; p.ldc = 256; p.K = 256;
        gemm_tc<128, false, 6><<<dim3(2, 64, 1), 256>>>(p);
    }
}

// round 7
// speedup vs baseline: 2.2829x; 1.0135x over previous
#include <cuda_runtime.h>
#include <cstdint>

// ---------------------------------------------------------------------------
// CaT transformer on tf32 mma.sync tensor cores (portable sm_100 target).
// B=16, N=512, D=256, H=8, HS=64, FF=1024, L=4.
// Every GEMM is D = A @ B^T with A,B K-major (mma row.col).
// O = P@V + A@V == (P + A) @ V  (mask folded into probabilities by softmax).
// R7: ldmatrix fragment loads + double-buffered smem (1 sync / chunk).
// ---------------------------------------------------------------------------

#define DI __device__ __forceinline__

static DI float swishf(float x) { return x / (1.f + __expf(-x)); }

// ------------------------- static device scratch ---------------------------
__device__ float g_Wqkvt[4 * 1536 * 256];   // [l][(t,h,hs)][d]
__device__ float g_Bqkv [4 * 1536];
__device__ float g_Wpt  [4 * 256 * 512];    // [l][n][k]
__device__ float g_W1t  [4 * 1024 * 256];
__device__ float g_W2t  [4 * 256 * 1024];
__device__ float g_Wlmt [256 * 256];
__device__ unsigned char g_Amask[2 * 512 * 512];
__device__ float g_KQV[3 * 512 * 8192];     // K[z][n][hs] | Qt[(z,hs)][n] | Vt[(z,hs)][n]
__device__ float g_AQ4[512 * 8192];         // [z][i][hs]
__device__ float g_Tb [128 * 512 * 512];    // scores / probs
__device__ float g_Ob [8192 * 512];
__device__ float g_Mha[8192 * 256];
__device__ float g_Ff [8192 * 1024];
__device__ float g_Xb [8192 * 256];

// ------------------------------ prep kernels -------------------------------
__global__ void pack_qkv_k(const float* __restrict__ Wk, const float* __restrict__ Wq,
                           const float* __restrict__ Wv, const float* __restrict__ bk,
                           const float* __restrict__ bq, const float* __restrict__ bv) {
    int idx = blockIdx.x * 256 + threadIdx.x;          // < 1572864
    int l = idx / 393216;                               // 1536*256 (NOT a power of 2)
    int rem = idx - l * 393216;
    int r = rem >> 8;
    int d = rem & 255;
    int t = r >> 9, h = (r >> 6) & 7, hs = r & 63;
    const float* W = (t == 0) ? Wk : (t == 1) ? Wq : Wv;
    g_Wqkvt[idx] = W[(((size_t)(l * 8 + h)) * 256 + d) * 64 + hs];
    if (idx < 4 * 1536) {
        int ll = idx / 1536;
        int c = idx - ll * 1536;
        int tt = c >> 9, hh = (c >> 6) & 7, hss = c & 63;
        const float* bb = (tt == 0) ? bk : (tt == 1) ? bq : bv;
        g_Bqkv[idx] = bb[(ll * 8 + hh) * 64 + hss];
    }
}

__global__ void pack_rest_k(const float* __restrict__ Wp, const float* __restrict__ W1,
                            const float* __restrict__ W2, const float* __restrict__ Wlm) {
    int idx = blockIdx.x * 256 + threadIdx.x;          // < 2686976
    if (idx < 524288) {                                 // Wpt [l][n(256)][k(512)]
        int l = idx >> 17, rem = idx & 131071;
        int n = rem >> 9, k = rem & 511;
        g_Wpt[idx] = Wp[((size_t)l * 512 + k) * 256 + n];
        return;
    }
    idx -= 524288;
    if (idx < 1048576) {                                // W1t [l][n(1024)][d(256)]
        int l = idx >> 18, rem = idx & 262143;
        int n = rem >> 8, d = rem & 255;
        g_W1t[idx] = W1[((size_t)l * 256 + d) * 1024 + n];
        return;
    }
    idx -= 1048576;
    if (idx < 1048576) {                                // W2t [l][n(256)][f(1024)]
        int l = idx >> 18, rem = idx & 262143;
        int n = rem >> 10, f = rem & 1023;
        g_W2t[idx] = W2[((size_t)l * 1024 + f) * 256 + n];
        return;
    }
    idx -= 1048576;
    if (idx < 65536) {                                  // Wlmt [n][d]
        int n = idx >> 8, d = idx & 255;
        g_Wlmt[idx] = Wlm[d * 256 + n];
    }
}

__global__ void mask_k(const int* __restrict__ dag) {
    int idx = blockIdx.x * 256 + threadIdx.x;          // < 524288
    int v = idx >> 18;
    int rem = idx & 262143;
    int i = rem >> 9;
    int j = rem & 511;
    g_Amask[idx] = (unsigned char)((dag[j * 512 + i] != 0 || (v && i == j)) ? 1 : 0);
}

// ------------------------------- GEMM core ---------------------------------
struct GP {
    const void*  A; const float* B; float* C;
    const float* bias; const float* res; const unsigned char* mask;
    float* dst0;
    int K, lda, ldb, ldc;
    long long sAz, sBz, sCz;
};

DI unsigned tf32_rn(float x) {
    unsigned r;
    asm("cvt.rn.tf32.f32 %0, %1;" : "=r"(r) : "f"(x));
    return r;
}

// MODE: 1 QKV scatter  2 score mask  3 AQ scatter  4 bias+swish
//       5 bias+residual  6 bias  7 PV scatter
template <int BN, bool AU8, int MODE>
__global__ __launch_bounds__(256) void gemm_tc(GP p) {
    constexpr int BM = 128, BK = 16, PITCH = 20;       // floats per smem row
    constexpr int WNW = (BN == 128) ? 4 : 2;           // warps along N
    constexpr int WM  = (BN == 128) ? 64 : 32;         // rows per warp
    constexpr int WN  = 32;                            // cols per warp
    constexpr int MT  = WM / 16, NT = WN / 8, NT2 = NT / 2;
    constexpr int ALD = 2;                             // A float4 loads / thread
    constexpr int BLD = (BN * BK) / (4 * 256);         // B float4 loads / thread
    constexpr int ASZ = BM * PITCH, BSZ = BN * PITCH;

    __shared__ __align__(16) float As[2][ASZ];
    __shared__ __align__(16) float Bs[2][BSZ];

    const int t = threadIdx.x, lane = t & 31, w = t >> 5;
    const int wm = w / WNW, wn = w % WNW;
    const int g = lane >> 2, cc = lane & 3;            // epilogue coords
    const int lrow = lane & 15;                        // ldmatrix row select
    const unsigned loff = (unsigned)((lane >> 4) << 4);// ldmatrix 16B half select
    const int bx = blockIdx.x, by = blockIdx.y, bz = blockIdx.z;

    const unsigned char* A8 = nullptr;
    const float* Af = nullptr;
    if (AU8) A8 = (const unsigned char*)p.A + (size_t)by * BM * p.lda;
    else     Af = (const float*)p.A + (size_t)bz * p.sAz + (size_t)by * BM * p.lda;
    const float* Bp = p.B + (size_t)bz * p.sBz + (size_t)bx * BN * p.ldb;
    float* C = p.C + (size_t)bz * p.sCz;

    const unsigned sA = (unsigned)__cvta_generic_to_shared(&As[0][0]);
    const unsigned sB = (unsigned)__cvta_generic_to_shared(&Bs[0][0]);

    float acc[MT][NT][4];
#pragma unroll
    for (int i = 0; i < MT; i++)
#pragma unroll
        for (int j = 0; j < NT; j++)
#pragma unroll
            for (int r = 0; r < 4; r++) acc[i][j][r] = 0.f;

    float4 avA[ALD], avB[BLD];

    auto loadG = [&](int k0) {
#pragma unroll
        for (int i = 0; i < ALD; i++) {
            const int idx = i * 256 + t;
            const int r = idx >> 2, c = (idx & 3) << 2;
            if (AU8) {
                uchar4 u = *(const uchar4*)(A8 + (size_t)r * p.lda + k0 + c);
                avA[i] = make_float4((float)u.x, (float)u.y, (float)u.z, (float)u.w);
            } else {
                avA[i] = *(const float4*)(Af + (size_t)r * p.lda + k0 + c);
            }
        }
#pragma unroll
        for (int i = 0; i < BLD; i++) {
            const int idx = i * 256 + t;
            const int r = idx >> 2, c = (idx & 3) << 2;
            avB[i] = *(const float4*)(Bp + (size_t)r * p.ldb + k0 + c);
        }
    };
    auto storeS = [&](int buf) {
#pragma unroll
        for (int i = 0; i < ALD; i++) {
            const int idx = i * 256 + t;
            const int r = idx >> 2, c = (idx & 3) << 2;
            unsigned w0 = tf32_rn(avA[i].x), w1 = tf32_rn(avA[i].y);
            unsigned w2 = tf32_rn(avA[i].z), w3 = tf32_rn(avA[i].w);
            asm volatile("st.shared.v4.b32 [%0], {%1,%2,%3,%4};"
                         :: "r"(sA + (unsigned)((buf * ASZ + r * PITCH + c) * 4)),
                            "r"(w0), "r"(w1), "r"(w2), "r"(w3));
        }
#pragma unroll
        for (int i = 0; i < BLD; i++) {
            const int idx = i * 256 + t;
            const int r = idx >> 2, c = (idx & 3) << 2;
            unsigned w0 = tf32_rn(avB[i].x), w1 = tf32_rn(avB[i].y);
            unsigned w2 = tf32_rn(avB[i].z), w3 = tf32_rn(avB[i].w);
            asm volatile("st.shared.v4.b32 [%0], {%1,%2,%3,%4};"
                         :: "r"(sB + (unsigned)((buf * BSZ + r * PITCH + c) * 4)),
                            "r"(w0), "r"(w1), "r"(w2), "r"(w3));
        }
    };

    const int nch = p.K >> 4;
    loadG(0);
    storeS(0);
    __syncthreads();
    for (int c = 0; c < nch; c++) {
        const int buf = c & 1;
        if (c + 1 < nch) loadG((c + 1) << 4);
        // ---- compute on smem buffer `buf` via ldmatrix ----
#pragma unroll
        for (int ks = 0; ks < 2; ks++) {
            unsigned a[MT][4], b[NT][2];
#pragma unroll
            for (int i = 0; i < MT; i++) {
                const unsigned addr = sA + (unsigned)((buf * ASZ
                                    + (wm * WM + i * 16 + lrow) * PITCH + ks * 8) * 4) + loff;
                asm volatile("ldmatrix.sync.aligned.m8n8.x4.shared.b16 {%0,%1,%2,%3}, [%4];"
                             : "=r"(a[i][0]), "=r"(a[i][1]), "=r"(a[i][2]), "=r"(a[i][3])
                             : "r"(addr));
            }
#pragma unroll
            for (int j2 = 0; j2 < NT2; j2++) {
                const unsigned addr = sB + (unsigned)((buf * BSZ
                                    + (wn * WN + j2 * 16 + lrow) * PITCH + ks * 8) * 4) + loff;
                asm volatile("ldmatrix.sync.aligned.m8n8.x4.shared.b16 {%0,%1,%2,%3}, [%4];"
                             : "=r"(b[2 * j2][0]), "=r"(b[2 * j2 + 1][0]),
                               "=r"(b[2 * j2][1]), "=r"(b[2 * j2 + 1][1])
                             : "r"(addr));
            }
#pragma unroll
            for (int i = 0; i < MT; i++)
#pragma unroll
                for (int j = 0; j < NT; j++)
                    asm volatile(
                        "mma.sync.aligned.m16n8k8.row.col.f32.tf32.tf32.f32 "
                        "{%0,%1,%2,%3}, {%4,%5,%6,%7}, {%8,%9}, {%0,%1,%2,%3};"
                        : "+f"(acc[i][j][0]), "+f"(acc[i][j][1]),
                          "+f"(acc[i][j][2]), "+f"(acc[i][j][3])
                        : "r"(a[i][0]), "r"(a[i][1]), "r"(a[i][2]), "r"(a[i][3]),
                          "r"(b[j][0]), "r"(b[j][1]));
        }
        if (c + 1 < nch) storeS((c + 1) & 1);
        __syncthreads();
    }

    // ------------------------------ epilogue -------------------------------
#pragma unroll
    for (int i = 0; i < MT; i++)
#pragma unroll
        for (int j = 0; j < NT; j++)
#pragma unroll
            for (int r = 0; r < 4; r++) {
                const int gm = by * BM + wm * WM + i * 16 + ((r >> 1) << 3) + g;
                const int gn = bx * BN + wn * WN + j * 8 + (cc << 1) + (r & 1);
                float v = acc[i][j][r];
                if (MODE == 1) {
                    v = swishf(v + p.bias[gn]);
                    const int tt = gn >> 9, h = (gn >> 6) & 7, hs = gn & 63;
                    const int b = gm >> 9, n = gm & 511, z = b * 8 + h;
                    if (tt == 0)      p.dst0[(size_t)(z * 512 + n) * 64 + hs] = v;
                    else if (tt == 1) p.dst0[4194304u + (size_t)(z * 64 + hs) * 512 + n] = v;
                    else              p.dst0[8388608u + (size_t)(z * 64 + hs) * 512 + n] = v;
                } else if (MODE == 2) {
                    v = p.mask[gm * 512 + gn] ? v * 0.125f : -3.0e38f;
                    C[(size_t)gm * p.ldc + gn] = v;
                } else if (MODE == 3) {
                    p.C[(size_t)(gn >> 6) * 32768 + (size_t)gm * 64 + (gn & 63)] = v;
                } else if (MODE == 4) {
                    C[(size_t)gm * p.ldc + gn] = swishf(v + p.bias[gn]);
                } else if (MODE == 5) {
                    C[(size_t)gm * p.ldc + gn] = v + p.bias[gn] + p.res[(size_t)gm * p.ldc + gn];
                } else if (MODE == 6) {
                    C[(size_t)gm * p.ldc + gn] = v + p.bias[gn];
                } else {   // MODE 7: PV out -> Ob[(b,i)][(h,hs)]
                    p.C[(size_t)((bz >> 3) * 512 + gm) * 512 + (bz & 7) * 64 + gn] = v;
                }
            }
}

// ----------------------- softmax (+ mask fold-in) --------------------------
__global__ void softmax_k(float* __restrict__ T, const unsigned char* __restrict__ M) {
    const int row  = blockIdx.x * 8 + (threadIdx.x >> 5);   // 65536 rows
    const int lane = threadIdx.x & 31;
    const int i = row & 511;
    float* r = T + (size_t)row * 512;
    const unsigned char* mr = M + i * 512;
    float x[16];
    float m = -3.4e38f;
#pragma unroll
    for (int k = 0; k < 16; k++) { x[k] = r[k * 32 + lane]; m = fmaxf(m, x[k]); }
#pragma unroll
    for (int o = 16; o; o >>= 1) m = fmaxf(m, __shfl_xor_sync(0xffffffffu, m, o));
    if (m <= -1e37f) {
#pragma unroll
        for (int k = 0; k < 16; k++) r[k * 32 + lane] = 0.f;
        return;
    }
    float s = 0.f;
#pragma unroll
    for (int k = 0; k < 16; k++) { x[k] = __expf(x[k] - m); s += x[k]; }
#pragma unroll
    for (int o = 16; o; o >>= 1) s += __shfl_xor_sync(0xffffffffu, s, o);
    const float inv = 1.f / s;
#pragma unroll
    for (int k = 0; k < 16; k++)
        r[k * 32 + lane] = x[k] * inv + (float)mr[k * 32 + lane];   // P + A
}

// ------------------------------ host driver --------------------------------
extern "C" void kernel_launch(void* const* d_in, const int* in_sizes, int n_in,
                              void* d_out, int out_size) {
    (void)in_sizes; (void)n_in; (void)out_size;
    const float* X   = (const float*)d_in[0];
    const int*   dag = (const int*)d_in[1];
    const float* Wk  = (const float*)d_in[2],  *bk  = (const float*)d_in[3];
    const float* Wq  = (const float*)d_in[4],  *bq  = (const float*)d_in[5];
    const float* Wv  = (const float*)d_in[6],  *bv  = (const float*)d_in[7];
    const float* Wp  = (const float*)d_in[8],  *bp  = (const float*)d_in[9];
    const float* W1  = (const float*)d_in[10], *b1  = (const float*)d_in[11];
    const float* W2  = (const float*)d_in[12], *b2  = (const float*)d_in[13];
    const float* Wlm = (const float*)d_in[14], *blm = (const float*)d_in[15];
    float* out = (float*)d_out;

    void* pv;
    cudaGetSymbolAddress(&pv, g_Wqkvt); float* Wqkvt = (float*)pv;
    cudaGetSymbolAddress(&pv, g_Bqkv);  float* Bqkv  = (float*)pv;
    cudaGetSymbolAddress(&pv, g_Wpt);   float* Wpt   = (float*)pv;
    cudaGetSymbolAddress(&pv, g_W1t);   float* W1t   = (float*)pv;
    cudaGetSymbolAddress(&pv, g_W2t);   float* W2t   = (float*)pv;
    cudaGetSymbolAddress(&pv, g_Wlmt);  float* Wlmt  = (float*)pv;
    cudaGetSymbolAddress(&pv, g_Amask); unsigned char* Amask = (unsigned char*)pv;
    cudaGetSymbolAddress(&pv, g_KQV);   float* KQV = (float*)pv;
    cudaGetSymbolAddress(&pv, g_AQ4);   float* AQ4 = (float*)pv;
    cudaGetSymbolAddress(&pv, g_Tb);    float* Tb  = (float*)pv;
    cudaGetSymbolAddress(&pv, g_Ob);    float* Ob  = (float*)pv;
    cudaGetSymbolAddress(&pv, g_Mha);   float* Mha = (float*)pv;
    cudaGetSymbolAddress(&pv, g_Ff);    float* Ff  = (float*)pv;
    cudaGetSymbolAddress(&pv, g_Xb);    float* Xb  = (float*)pv;

    pack_qkv_k<<<6144, 256>>>(Wk, Wq, Wv, bk, bq, bv);
    pack_rest_k<<<10496, 256>>>(Wp, W1, W2, Wlm);
    mask_k<<<2048, 256>>>(dag);

    for (int l = 0; l < 4; l++) {
        const unsigned char* Am = Amask + (l ? 262144 : 0);
        {   // QKV: X @ Wqkvt^T -> scatter K/Qt/Vt (+bias+swish)
            GP p{}; p.A = (l == 0) ? (const void*)X : (const void*)Xb; p.lda = 256;
            p.B = Wqkvt + (size_t)l * 1536 * 256; p.ldb = 256;
            p.bias = Bqkv + l * 1536; p.dst0 = KQV; p.K = 256;
            gemm_tc<128, false, 1><<<dim3(12, 64, 1), 256>>>(p);
        }
        {   // AQ = mask @ Qt^T  -> AQ4[z][i][hs]
            GP p{}; p.A = Am; p.lda = 512;
            p.B = KQV + 4194304; p.ldb = 512;
            p.C = AQ4; p.K = 512;
            gemm_tc<128, true, 3><<<dim3(64, 4, 1), 256>>>(p);
        }
        {   // scores = (AQ4 @ K^T)/8, masked -> Tb   (z over 128 bh)
            GP p{}; p.A = AQ4; p.lda = 64; p.sAz = 32768;
            p.B = KQV; p.ldb = 64; p.sBz = 32768;
            p.C = Tb; p.ldc = 512; p.sCz = 262144; p.mask = Am; p.K = 64;
            gemm_tc<128, false, 2><<<dim3(4, 4, 128), 256>>>(p);
        }
        softmax_k<<<8192, 256>>>(Tb, Am);
        {   // O = (P+A) @ Vt^T -> Ob[(b,i)][(h,hs)]
            GP p{}; p.A = Tb; p.lda = 512; p.sAz = 262144;
            p.B = KQV + 2 * 4194304; p.ldb = 512; p.sBz = 32768;
            p.C = Ob; p.K = 512;
            gemm_tc<64, false, 7><<<dim3(1, 4, 128), 256>>>(p);
        }
        {   // mha = swish(Ob @ Wpt^T + bp)
            GP p{}; p.A = Ob; p.lda = 512;
            p.B = Wpt + (size_t)l * 256 * 512; p.ldb = 512;
            p.bias = bp + l * 256; p.C = Mha; p.ldc = 256; p.K = 512;
            gemm_tc<128, false, 4><<<dim3(2, 64, 1), 256>>>(p);
        }
        {   // ff = swish(mha @ W1t^T + b1)
            GP p{}; p.A = Mha; p.lda = 256;
            p.B = W1t + (size_t)l * 1024 * 256; p.ldb = 256;
            p.bias = b1 + l * 1024; p.C = Ff; p.ldc = 1024; p.K = 256;
            gemm_tc<128, false, 4><<<dim3(8, 64, 1), 256>>>(p);
        }
        {   // X = ff @ W2t^T + b2 + mha
            GP p{}; p.A = Ff; p.lda = 1024;
            p.B = W2t + (size_t)l * 256 * 1024; p.ldb = 1024;
            p.bias = b2 + l * 256; p.res = Mha; p.C = Xb; p.ldc = 256; p.K = 1024;
            gemm_tc<128, false, 5><<<dim3(2, 64, 1), 256>>>(p);
        }
    }
    {   // lm head
        GP p{}; p.A = Xb; p.lda = 256; p.B = Wlmt; p.ldb = 256;
        p.bias = blm; p.C = out; p.ldc = 256; p.K = 256;
        gemm_tc<128, false, 6><<<dim3(2, 64, 1), 256>>>(p);
    }
}

// round 8
// speedup vs baseline: 2.3934x; 1.0484x over previous
#include <cuda_runtime.h>
#include <cstdint>

// ---------------------------------------------------------------------------
// CaT transformer, tf32 mma.sync (portable sm_100 target).
// B=16, N=512, D=256, H=8, HS=64, FF=1024, L=4.
// R8: fused attention kernel (scores + softmax + PV in one CTA, exact softmax;
//     64 rows/CTA, S tile resident in smem). Math order identical to R7.
// ---------------------------------------------------------------------------

#define DI __device__ __forceinline__

static DI float swishf(float x) { return x / (1.f + __expf(-x)); }

// ------------------------- static device scratch ---------------------------
__device__ float g_Wqkvt[4 * 1536 * 256];   // [l][(t,h,hs)][d]
__device__ float g_Bqkv [4 * 1536];
__device__ float g_Wpt  [4 * 256 * 512];    // [l][n][k]
__device__ float g_W1t  [4 * 1024 * 256];
__device__ float g_W2t  [4 * 256 * 1024];
__device__ float g_Wlmt [256 * 256];
__device__ unsigned char g_Amask[2 * 512 * 512];
__device__ float g_KQV[3 * 512 * 8192];     // K[z][n][hs] | Qt[(z,hs)][n] | Vt[(z,hs)][n]
__device__ float g_AQ4[512 * 8192];         // [z][i][hs]
__device__ float g_Ob [8192 * 512];
__device__ float g_Mha[8192 * 256];
__device__ float g_Ff [8192 * 1024];
__device__ float g_Xb [8192 * 256];

// ------------------------------ prep kernels -------------------------------
__global__ void pack_qkv_k(const float* __restrict__ Wk, const float* __restrict__ Wq,
                           const float* __restrict__ Wv, const float* __restrict__ bk,
                           const float* __restrict__ bq, const float* __restrict__ bv) {
    int idx = blockIdx.x * 256 + threadIdx.x;          // < 1572864
    int l = idx / 393216;                               // 1536*256
    int rem = idx - l * 393216;
    int r = rem >> 8;
    int d = rem & 255;
    int t = r >> 9, h = (r >> 6) & 7, hs = r & 63;
    const float* W = (t == 0) ? Wk : (t == 1) ? Wq : Wv;
    g_Wqkvt[idx] = W[(((size_t)(l * 8 + h)) * 256 + d) * 64 + hs];
    if (idx < 4 * 1536) {
        int ll = idx / 1536;
        int c = idx - ll * 1536;
        int tt = c >> 9, hh = (c >> 6) & 7, hss = c & 63;
        const float* bb = (tt == 0) ? bk : (tt == 1) ? bq : bv;
        g_Bqkv[idx] = bb[(ll * 8 + hh) * 64 + hss];
    }
}

__global__ void pack_rest_k(const float* __restrict__ Wp, const float* __restrict__ W1,
                            const float* __restrict__ W2, const float* __restrict__ Wlm) {
    int idx = blockIdx.x * 256 + threadIdx.x;          // < 2686976
    if (idx < 524288) {                                 // Wpt [l][n(256)][k(512)]
        int l = idx >> 17, rem = idx & 131071;
        int n = rem >> 9, k = rem & 511;
        g_Wpt[idx] = Wp[((size_t)l * 512 + k) * 256 + n];
        return;
    }
    idx -= 524288;
    if (idx < 1048576) {                                // W1t [l][n(1024)][d(256)]
        int l = idx >> 18, rem = idx & 262143;
        int n = rem >> 8, d = rem & 255;
        g_W1t[idx] = W1[((size_t)l * 256 + d) * 1024 + n];
        return;
    }
    idx -= 1048576;
    if (idx < 1048576) {                                // W2t [l][n(256)][f(1024)]
        int l = idx >> 18, rem = idx & 262143;
        int n = rem >> 10, f = rem & 1023;
        g_W2t[idx] = W2[((size_t)l * 1024 + f) * 256 + n];
        return;
    }
    idx -= 1048576;
    if (idx < 65536) {                                  // Wlmt [n][d]
        int n = idx >> 8, d = idx & 255;
        g_Wlmt[idx] = Wlm[d * 256 + n];
    }
}

__global__ void mask_k(const int* __restrict__ dag) {
    int idx = blockIdx.x * 256 + threadIdx.x;          // < 524288
    int v = idx >> 18;
    int rem = idx & 262143;
    int i = rem >> 9;
    int j = rem & 511;
    g_Amask[idx] = (unsigned char)((dag[j * 512 + i] != 0 || (v && i == j)) ? 1 : 0);
}

// --------------------------- shared helpers --------------------------------
DI unsigned tf32_rn(float x) {
    unsigned r;
    asm("cvt.rn.tf32.f32 %0, %1;" : "=r"(r) : "f"(x));
    return r;
}
DI unsigned cvta_s(const void* p) { return (unsigned)__cvta_generic_to_shared(p); }

#define LDM_X4(r0, r1, r2, r3, addr) \
    asm volatile("ldmatrix.sync.aligned.m8n8.x4.shared.b16 {%0,%1,%2,%3}, [%4];" \
                 : "=r"(r0), "=r"(r1), "=r"(r2), "=r"(r3) : "r"(addr))
#define MMA_TF32(d, a, b) \
    asm volatile("mma.sync.aligned.m16n8k8.row.col.f32.tf32.tf32.f32 " \
                 "{%0,%1,%2,%3}, {%4,%5,%6,%7}, {%8,%9}, {%0,%1,%2,%3};" \
                 : "+f"((d)[0]), "+f"((d)[1]), "+f"((d)[2]), "+f"((d)[3]) \
                 : "r"((a)[0]), "r"((a)[1]), "r"((a)[2]), "r"((a)[3]), \
                   "r"((b)[0]), "r"((b)[1]))
#define STS4(addr, w0, w1, w2, w3) \
    asm volatile("st.shared.v4.b32 [%0], {%1,%2,%3,%4};" \
                 :: "r"(addr), "r"(w0), "r"(w1), "r"(w2), "r"(w3))

// ------------------------------- GEMM core ---------------------------------
struct GP {
    const void*  A; const float* B; float* C;
    const float* bias; const float* res;
    float* dst0;
    int K, lda, ldb, ldc;
    long long sAz, sBz, sCz;
};

// MODE: 1 QKV scatter  3 AQ scatter  4 bias+swish  5 bias+residual  6 bias
template <int BN, bool AU8, int MODE>
__global__ __launch_bounds__(256) void gemm_tc(GP p) {
    constexpr int BM = 128, BK = 16, PITCH = 20;
    constexpr int WNW = (BN == 128) ? 4 : 2;
    constexpr int WM  = (BN == 128) ? 64 : 32;
    constexpr int WN  = 32;
    constexpr int MT  = WM / 16, NT = WN / 8, NT2 = NT / 2;
    constexpr int ALD = 2;
    constexpr int BLD = (BN * BK) / (4 * 256);
    constexpr int ASZ = BM * PITCH, BSZ = BN * PITCH;

    __shared__ __align__(16) float As[2][ASZ];
    __shared__ __align__(16) float Bs[2][BSZ];

    const int t = threadIdx.x, lane = t & 31, w = t >> 5;
    const int wm = w / WNW, wn = w % WNW;
    const int g = lane >> 2, cc = lane & 3;
    const int lrow = lane & 15;
    const unsigned loff = (unsigned)((lane >> 4) << 4);
    const int bx = blockIdx.x, by = blockIdx.y, bz = blockIdx.z;

    const unsigned char* A8 = nullptr;
    const float* Af = nullptr;
    if (AU8) A8 = (const unsigned char*)p.A + (size_t)by * BM * p.lda;
    else     Af = (const float*)p.A + (size_t)bz * p.sAz + (size_t)by * BM * p.lda;
    const float* Bp = p.B + (size_t)bz * p.sBz + (size_t)bx * BN * p.ldb;
    float* C = p.C + (size_t)bz * p.sCz;

    const unsigned sA = cvta_s(&As[0][0]);
    const unsigned sB = cvta_s(&Bs[0][0]);

    float acc[MT][NT][4];
#pragma unroll
    for (int i = 0; i < MT; i++)
#pragma unroll
        for (int j = 0; j < NT; j++)
#pragma unroll
            for (int r = 0; r < 4; r++) acc[i][j][r] = 0.f;

    float4 avA[ALD], avB[BLD];

    auto loadG = [&](int k0) {
#pragma unroll
        for (int i = 0; i < ALD; i++) {
            const int idx = i * 256 + t;
            const int r = idx >> 2, c = (idx & 3) << 2;
            if (AU8) {
                uchar4 u = *(const uchar4*)(A8 + (size_t)r * p.lda + k0 + c);
                avA[i] = make_float4((float)u.x, (float)u.y, (float)u.z, (float)u.w);
            } else {
                avA[i] = *(const float4*)(Af + (size_t)r * p.lda + k0 + c);
            }
        }
#pragma unroll
        for (int i = 0; i < BLD; i++) {
            const int idx = i * 256 + t;
            const int r = idx >> 2, c = (idx & 3) << 2;
            avB[i] = *(const float4*)(Bp + (size_t)r * p.ldb + k0 + c);
        }
    };
    auto storeS = [&](int buf) {
#pragma unroll
        for (int i = 0; i < ALD; i++) {
            const int idx = i * 256 + t;
            const int r = idx >> 2, c = (idx & 3) << 2;
            STS4(sA + (unsigned)((buf * ASZ + r * PITCH + c) * 4),
                 tf32_rn(avA[i].x), tf32_rn(avA[i].y), tf32_rn(avA[i].z), tf32_rn(avA[i].w));
        }
#pragma unroll
        for (int i = 0; i < BLD; i++) {
            const int idx = i * 256 + t;
            const int r = idx >> 2, c = (idx & 3) << 2;
            STS4(sB + (unsigned)((buf * BSZ + r * PITCH + c) * 4),
                 tf32_rn(avB[i].x), tf32_rn(avB[i].y), tf32_rn(avB[i].z), tf32_rn(avB[i].w));
        }
    };

    const int nch = p.K >> 4;
    loadG(0);
    storeS(0);
    __syncthreads();
    for (int c = 0; c < nch; c++) {
        const int buf = c & 1;
        if (c + 1 < nch) loadG((c + 1) << 4);
#pragma unroll
        for (int ks = 0; ks < 2; ks++) {
            unsigned a[MT][4], b[NT][2];
#pragma unroll
            for (int i = 0; i < MT; i++) {
                const unsigned addr = sA + (unsigned)((buf * ASZ
                                    + (wm * WM + i * 16 + lrow) * PITCH + ks * 8) * 4) + loff;
                LDM_X4(a[i][0], a[i][1], a[i][2], a[i][3], addr);
            }
#pragma unroll
            for (int j2 = 0; j2 < NT2; j2++) {
                const unsigned addr = sB + (unsigned)((buf * BSZ
                                    + (wn * WN + j2 * 16 + lrow) * PITCH + ks * 8) * 4) + loff;
                LDM_X4(b[2 * j2][0], b[2 * j2 + 1][0], b[2 * j2][1], b[2 * j2 + 1][1], addr);
            }
#pragma unroll
            for (int i = 0; i < MT; i++)
#pragma unroll
                for (int j = 0; j < NT; j++)
                    MMA_TF32(acc[i][j], a[i], b[j]);
        }
        if (c + 1 < nch) storeS((c + 1) & 1);
        __syncthreads();
    }

#pragma unroll
    for (int i = 0; i < MT; i++)
#pragma unroll
        for (int j = 0; j < NT; j++)
#pragma unroll
            for (int r = 0; r < 4; r++) {
                const int gm = by * BM + wm * WM + i * 16 + ((r >> 1) << 3) + g;
                const int gn = bx * BN + wn * WN + j * 8 + (cc << 1) + (r & 1);
                float v = acc[i][j][r];
                if (MODE == 1) {
                    v = swishf(v + p.bias[gn]);
                    const int tt = gn >> 9, h = (gn >> 6) & 7, hs = gn & 63;
                    const int b = gm >> 9, n = gm & 511, z = b * 8 + h;
                    if (tt == 0)      p.dst0[(size_t)(z * 512 + n) * 64 + hs] = v;
                    else if (tt == 1) p.dst0[4194304u + (size_t)(z * 64 + hs) * 512 + n] = v;
                    else              p.dst0[8388608u + (size_t)(z * 64 + hs) * 512 + n] = v;
                } else if (MODE == 3) {
                    p.C[(size_t)(gn >> 6) * 32768 + (size_t)gm * 64 + (gn & 63)] = v;
                } else if (MODE == 4) {
                    C[(size_t)gm * p.ldc + gn] = swishf(v + p.bias[gn]);
                } else if (MODE == 5) {
                    C[(size_t)gm * p.ldc + gn] = v + p.bias[gn] + p.res[(size_t)gm * p.ldc + gn];
                } else {
                    C[(size_t)gm * p.ldc + gn] = v + p.bias[gn];
                }
            }
}

// ------------------- fused attention: scores+softmax+PV --------------------
// Grid (8 i-tiles, 128 z).  CTA: 64 attention rows, full 512 cols in smem.
// smem (floats): S 64x516 @0 | At 64x68 @33024 | Bt 2x(128x68) @37376
static const int ATTN_SMEM = (33024 + 4352 + 17408) * 4;   // 219136 B

__global__ __launch_bounds__(256) void attn_k(
    const float* __restrict__ AQ, const float* __restrict__ Kb,
    const float* __restrict__ Vt, const unsigned char* __restrict__ Mk,
    float* __restrict__ Ob) {
    extern __shared__ float sm[];
    float* S  = sm;
    float* At = sm + 33024;
    float* Bt = sm + 37376;

    const int t = threadIdx.x, lane = t & 31, w = t >> 5;
    const int g = lane >> 2, cc = lane & 3;
    const int lrow = lane & 15;
    const unsigned loff = (unsigned)((lane >> 4) << 4);
    const int i0 = blockIdx.x * 64, z = blockIdx.y;

    const float* AQz = AQ + (size_t)z * 32768 + (size_t)i0 * 64;   // 64 x 64
    const float* Kp  = Kb + (size_t)z * 32768;                     // 512 x 64
    const float* Vz  = Vt + (size_t)z * 32768;                     // 64 x 512

    const unsigned sS = cvta_s(S), sA = cvta_s(At), sB = cvta_s(Bt);

    // ---- stage AQ tile (tf32, pitch 68) ----
#pragma unroll
    for (int i = 0; i < 4; i++) {
        const int idx = i * 256 + t;
        const int r = idx >> 4, c = (idx & 15) << 2;
        float4 v = *(const float4*)(AQz + r * 64 + c);
        STS4(sA + (unsigned)((r * 68 + c) * 4),
             tf32_rn(v.x), tf32_rn(v.y), tf32_rn(v.z), tf32_rn(v.w));
    }

    // ================= phase 1: S = AQ @ K^T, mask+scale =================
    {
        const int wm = w >> 2, wn = w & 3;      // WM=32 (MT=2), WN=32 (NT=4)
        float acc[2][4][4];
        float4 kv[8];
        auto loadK = [&](int jc) {
#pragma unroll
            for (int i = 0; i < 8; i++) {
                const int idx = i * 256 + t;
                const int r = idx >> 4, c = (idx & 15) << 2;
                kv[i] = *(const float4*)(Kp + (size_t)(jc * 128 + r) * 64 + c);
            }
        };
        auto storeK = [&](int buf) {
#pragma unroll
            for (int i = 0; i < 8; i++) {
                const int idx = i * 256 + t;
                const int r = idx >> 4, c = (idx & 15) << 2;
                STS4(sB + (unsigned)((buf * 8704 + r * 68 + c) * 4),
                     tf32_rn(kv[i].x), tf32_rn(kv[i].y), tf32_rn(kv[i].z), tf32_rn(kv[i].w));
            }
        };
        loadK(0); storeK(0); __syncthreads();
        for (int jc = 0; jc < 4; jc++) {
            const int buf = jc & 1;
#pragma unroll
            for (int i = 0; i < 2; i++)
#pragma unroll
                for (int j = 0; j < 4; j++)
#pragma unroll
                    for (int r = 0; r < 4; r++) acc[i][j][r] = 0.f;
            if (jc + 1 < 4) loadK(jc + 1);
#pragma unroll
            for (int ks = 0; ks < 8; ks++) {
                unsigned a[2][4], b[4][2];
#pragma unroll
                for (int i = 0; i < 2; i++) {
                    const unsigned addr = sA + (unsigned)(((wm * 32 + i * 16 + lrow) * 68
                                        + ks * 8) * 4) + loff;
                    LDM_X4(a[i][0], a[i][1], a[i][2], a[i][3], addr);
                }
#pragma unroll
                for (int j2 = 0; j2 < 2; j2++) {
                    const unsigned addr = sB + (unsigned)((buf * 8704
                                        + (wn * 32 + j2 * 16 + lrow) * 68 + ks * 8) * 4) + loff;
                    LDM_X4(b[2 * j2][0], b[2 * j2 + 1][0], b[2 * j2][1], b[2 * j2 + 1][1], addr);
                }
#pragma unroll
                for (int i = 0; i < 2; i++)
#pragma unroll
                    for (int j = 0; j < 4; j++)
                        MMA_TF32(acc[i][j], a[i], b[j]);
            }
            if (jc + 1 < 4) storeK((jc + 1) & 1);
            // epilogue: mask+scale -> S
#pragma unroll
            for (int i = 0; i < 2; i++)
#pragma unroll
                for (int j = 0; j < 4; j++)
#pragma unroll
                    for (int r = 0; r < 4; r++) {
                        const int gm = wm * 32 + i * 16 + ((r >> 1) << 3) + g;
                        const int gn = jc * 128 + wn * 32 + j * 8 + (cc << 1) + (r & 1);
                        const float v = acc[i][j][r];
                        S[gm * 516 + gn] =
                            Mk[(size_t)(i0 + gm) * 512 + gn] ? v * 0.125f : -3.0e38f;
                    }
            __syncthreads();
        }
    }

    // ================= phase 2: exact softmax + (P + A), tf32 ============
    for (int it = 0; it < 8; it++) {
        const int ir = it * 8 + w;
        float* r = S + ir * 516;
        const unsigned char* mr = Mk + (size_t)(i0 + ir) * 512;
        float x[16];
        float m = -3.4e38f;
#pragma unroll
        for (int k = 0; k < 16; k++) { x[k] = r[k * 32 + lane]; m = fmaxf(m, x[k]); }
#pragma unroll
        for (int o = 16; o; o >>= 1) m = fmaxf(m, __shfl_xor_sync(0xffffffffu, m, o));
        if (m <= -1e37f) {
#pragma unroll
            for (int k = 0; k < 16; k++) r[k * 32 + lane] = 0.f;
        } else {
            float s = 0.f;
#pragma unroll
            for (int k = 0; k < 16; k++) { x[k] = __expf(x[k] - m); s += x[k]; }
#pragma unroll
            for (int o = 16; o; o >>= 1) s += __shfl_xor_sync(0xffffffffu, s, o);
            const float inv = 1.f / s;
#pragma unroll
            for (int k = 0; k < 16; k++)
                r[k * 32 + lane] = __uint_as_float(
                    tf32_rn(x[k] * inv + (float)mr[k * 32 + lane]));
        }
    }
    __syncthreads();

    // ================= phase 3: O = Ssm @ V^T =============================
    {
        const int wm = w >> 2, wn = w & 3;      // WM=32 (MT=2), WN=16 (NT=2)
        float oa[2][2][4];
#pragma unroll
        for (int i = 0; i < 2; i++)
#pragma unroll
            for (int j = 0; j < 2; j++)
#pragma unroll
                for (int r = 0; r < 4; r++) oa[i][j][r] = 0.f;
        float4 vv;
        const int vr = t >> 2, vc = (t & 3) << 2;
        auto loadV  = [&](int kc) { vv = *(const float4*)(Vz + (size_t)vr * 512 + kc * 16 + vc); };
        auto storeV = [&](int buf) {
            STS4(sB + (unsigned)((buf * 1280 + vr * 20 + vc) * 4),
                 tf32_rn(vv.x), tf32_rn(vv.y), tf32_rn(vv.z), tf32_rn(vv.w));
        };
        loadV(0); storeV(0); __syncthreads();
        for (int kc = 0; kc < 32; kc++) {
            const int buf = kc & 1;
            if (kc + 1 < 32) loadV(kc + 1);
#pragma unroll
            for (int ks = 0; ks < 2; ks++) {
                unsigned a[2][4], b[2][2];
#pragma unroll
                for (int i = 0; i < 2; i++) {
                    const unsigned addr = sS + (unsigned)(((wm * 32 + i * 16 + lrow) * 516
                                        + kc * 16 + ks * 8) * 4) + loff;
                    LDM_X4(a[i][0], a[i][1], a[i][2], a[i][3], addr);
                }
                {
                    const unsigned addr = sB + (unsigned)((buf * 1280
                                        + (wn * 16 + lrow) * 20 + ks * 8) * 4) + loff;
                    LDM_X4(b[0][0], b[1][0], b[0][1], b[1][1], addr);
                }
#pragma unroll
                for (int i = 0; i < 2; i++)
#pragma unroll
                    for (int j = 0; j < 2; j++)
                        MMA_TF32(oa[i][j], a[i], b[j]);
            }
            if (kc + 1 < 32) storeV((kc + 1) & 1);
            __syncthreads();
        }
        // epilogue -> Ob[(b*512 + i)][(h*64 + hs)]
        const int b = z >> 3, h = z & 7;
#pragma unroll
        for (int i = 0; i < 2; i++)
#pragma unroll
            for (int j = 0; j < 2; j++)
#pragma unroll
                for (int r = 0; r < 4; r++) {
                    const int gm = wm * 32 + i * 16 + ((r >> 1) << 3) + g;
                    const int gn = wn * 16 + j * 8 + (cc << 1) + (r & 1);
                    Ob[(size_t)(b * 512 + i0 + gm) * 512 + h * 64 + gn] = oa[i][j][r];
                }
    }
}

// ------------------------------ host driver --------------------------------
extern "C" void kernel_launch(void* const* d_in, const int* in_sizes, int n_in,
                              void* d_out, int out_size) {
    (void)in_sizes; (void)n_in; (void)out_size;
    const float* X   = (const float*)d_in[0];
    const int*   dag = (const int*)d_in[1];
    const float* Wk  = (const float*)d_in[2],  *bk  = (const float*)d_in[3];
    const float* Wq  = (const float*)d_in[4],  *bq  = (const float*)d_in[5];
    const float* Wv  = (const float*)d_in[6],  *bv  = (const float*)d_in[7];
    const float* Wp  = (const float*)d_in[8],  *bp  = (const float*)d_in[9];
    const float* W1  = (const float*)d_in[10], *b1  = (const float*)d_in[11];
    const float* W2  = (const float*)d_in[12], *b2  = (const float*)d_in[13];
    const float* Wlm = (const float*)d_in[14], *blm = (const float*)d_in[15];
    float* out = (float*)d_out;

    cudaFuncSetAttribute(attn_k, cudaFuncAttributeMaxDynamicSharedMemorySize, ATTN_SMEM);

    void* pv;
    cudaGetSymbolAddress(&pv, g_Wqkvt); float* Wqkvt = (float*)pv;
    cudaGetSymbolAddress(&pv, g_Bqkv);  float* Bqkv  = (float*)pv;
    cudaGetSymbolAddress(&pv, g_Wpt);   float* Wpt   = (float*)pv;
    cudaGetSymbolAddress(&pv, g_W1t);   float* W1t   = (float*)pv;
    cudaGetSymbolAddress(&pv, g_W2t);   float* W2t   = (float*)pv;
    cudaGetSymbolAddress(&pv, g_Wlmt);  float* Wlmt  = (float*)pv;
    cudaGetSymbolAddress(&pv, g_Amask); unsigned char* Amask = (unsigned char*)pv;
    cudaGetSymbolAddress(&pv, g_KQV);   float* KQV = (float*)pv;
    cudaGetSymbolAddress(&pv, g_AQ4);   float* AQ4 = (float*)pv;
    cudaGetSymbolAddress(&pv, g_Ob);    float* Ob  = (float*)pv;
    cudaGetSymbolAddress(&pv, g_Mha);   float* Mha = (float*)pv;
    cudaGetSymbolAddress(&pv, g_Ff);    float* Ff  = (float*)pv;
    cudaGetSymbolAddress(&pv, g_Xb);    float* Xb  = (float*)pv;

    pack_qkv_k<<<6144, 256>>>(Wk, Wq, Wv, bk, bq, bv);
    pack_rest_k<<<10496, 256>>>(Wp, W1, W2, Wlm);
    mask_k<<<2048, 256>>>(dag);

    for (int l = 0; l < 4; l++) {
        const unsigned char* Am = Amask + (l ? 262144 : 0);
        {   // QKV: X @ Wqkvt^T -> scatter K/Qt/Vt (+bias+swish)
            GP p{}; p.A = (l == 0) ? (const void*)X : (const void*)Xb; p.lda = 256;
            p.B = Wqkvt + (size_t)l * 1536 * 256; p.ldb = 256;
            p.bias = Bqkv + l * 1536; p.dst0 = KQV; p.K = 256;
            gemm_tc<128, false, 1><<<dim3(12, 64, 1), 256>>>(p);
        }
        {   // AQ = mask @ Qt^T -> AQ4[z][i][hs]
            GP p{}; p.A = Am; p.lda = 512;
            p.B = KQV + 4194304; p.ldb = 512;
            p.C = AQ4; p.K = 512;
            gemm_tc<128, true, 3><<<dim3(64, 4, 1), 256>>>(p);
        }
        // fused scores + softmax + PV
        attn_k<<<dim3(8, 128), 256, ATTN_SMEM>>>(AQ4, KQV, KQV + 2 * 4194304, Am, Ob);
        {   // mha = swish(Ob @ Wpt^T + bp)
            GP p{}; p.A = Ob; p.lda = 512;
            p.B = Wpt + (size_t)l * 256 * 512; p.ldb = 512;
            p.bias = bp + l * 256; p.C = Mha; p.ldc = 256; p.K = 512;
            gemm_tc<128, false, 4><<<dim3(2, 64, 1), 256>>>(p);
        }
        {   // ff = swish(mha @ W1t^T + b1)
            GP p{}; p.A = Mha; p.lda = 256;
            p.B = W1t + (size_t)l * 1024 * 256; p.ldb = 256;
            p.bias = b1 + l * 1024; p.C = Ff; p.ldc = 1024; p.K = 256;
            gemm_tc<128, false, 4><<<dim3(8, 64, 1), 256>>>(p);
        }
        {   // X = ff @ W2t^T + b2 + mha
            GP p{}; p.A = Ff; p.lda = 1024;
            p.B = W2t + (size_t)l * 256 * 1024; p.ldb = 1024;
            p.bias = b2 + l * 256; p.res = Mha; p.C = Xb; p.ldc = 256; p.K = 1024;
            gemm_tc<128, false, 5><<<dim3(2, 64, 1), 256>>>(p);
        }
    }
    {   // lm head
        GP p{}; p.A = Xb; p.lda = 256; p.B = Wlmt; p.ldb = 256;
        p.bias = blm; p.C = out; p.ldc = 256; p.K = 256;
        gemm_tc<128, false, 6><<<dim3(2, 64, 1), 256>>>(p);
    }
}

// round 9
// speedup vs baseline: 2.4693x; 1.0317x over previous
#include <cuda_runtime.h>
#include <cstdint>

// ---------------------------------------------------------------------------
// CaT transformer, tf32 mma.sync (portable sm_100 target).
// R9: all GEMM operands pre-rounded to tf32 at the producer (RN, idempotent),
// so GEMMs use raw cp.async 4-stage pipelines with no cvt/staging.
// Numerics bit-identical to R8 (rel_err oracle: 7.903782e-4).
// ---------------------------------------------------------------------------

#define DI __device__ __forceinline__

static DI float swishf(float x) { return x / (1.f + __expf(-x)); }

// ------------------------- static device scratch ---------------------------
__device__ float g_Wqkvt[4 * 1536 * 256];   // [l][(t,h,hs)][d]   tf32
__device__ float g_Bqkv [4 * 1536];
__device__ float g_Wpt  [4 * 256 * 512];    // tf32
__device__ float g_W1t  [4 * 1024 * 256];   // tf32
__device__ float g_W2t  [4 * 256 * 1024];   // tf32
__device__ float g_Wlmt [256 * 256];        // tf32
__device__ unsigned char g_Amask[2 * 512 * 512];
__device__ float g_Amaskf[2 * 512 * 512];   // 0.0 / 1.0 (tf32-exact)
__device__ float g_KQV[3 * 512 * 8192];     // K | Qt | Vt   (tf32)
__device__ float g_AQ4[512 * 8192];         // [z][i][hs]    (tf32)
__device__ float g_Ob [8192 * 512];         // tf32
__device__ float g_Mha[8192 * 256];         // exact (residual)
__device__ float g_Mhar[8192 * 256];        // tf32 (GEMM input)
__device__ float g_Ff [8192 * 1024];        // tf32
__device__ float g_Xb [8192 * 256];         // tf32

// --------------------------- helpers ---------------------------------------
DI unsigned tf32_rn(float x) {
    unsigned r;
    asm("cvt.rn.tf32.f32 %0, %1;" : "=r"(r) : "f"(x));
    return r;
}
DI float tf32f(float x) { return __uint_as_float(tf32_rn(x)); }
DI unsigned cvta_s(const void* p) { return (unsigned)__cvta_generic_to_shared(p); }
DI void cpa16(unsigned dst, const void* src) {
    asm volatile("cp.async.cg.shared.global [%0], [%1], 16;" :: "r"(dst), "l"(src) : "memory");
}
#define CPA_COMMIT() asm volatile("cp.async.commit_group;" ::: "memory")
#define CPA_WAIT(N)  asm volatile("cp.async.wait_group %0;" :: "n"(N) : "memory")

#define LDM_X4(r0, r1, r2, r3, addr) \
    asm volatile("ldmatrix.sync.aligned.m8n8.x4.shared.b16 {%0,%1,%2,%3}, [%4];" \
                 : "=r"(r0), "=r"(r1), "=r"(r2), "=r"(r3) : "r"(addr))
#define MMA_TF32(d, a, b) \
    asm volatile("mma.sync.aligned.m16n8k8.row.col.f32.tf32.tf32.f32 " \
                 "{%0,%1,%2,%3}, {%4,%5,%6,%7}, {%8,%9}, {%0,%1,%2,%3};" \
                 : "+f"((d)[0]), "+f"((d)[1]), "+f"((d)[2]), "+f"((d)[3]) \
                 : "r"((a)[0]), "r"((a)[1]), "r"((a)[2]), "r"((a)[3]), \
                   "r"((b)[0]), "r"((b)[1]))

// ------------------------------ prep kernels -------------------------------
__global__ void pack_qkv_k(const float* __restrict__ Wk, const float* __restrict__ Wq,
                           const float* __restrict__ Wv, const float* __restrict__ bk,
                           const float* __restrict__ bq, const float* __restrict__ bv) {
    int idx = blockIdx.x * 256 + threadIdx.x;          // < 1572864
    int l = idx / 393216;
    int rem = idx - l * 393216;
    int r = rem >> 8;
    int d = rem & 255;
    int t = r >> 9, h = (r >> 6) & 7, hs = r & 63;
    const float* W = (t == 0) ? Wk : (t == 1) ? Wq : Wv;
    g_Wqkvt[idx] = tf32f(W[(((size_t)(l * 8 + h)) * 256 + d) * 64 + hs]);
    if (idx < 4 * 1536) {
        int ll = idx / 1536;
        int c = idx - ll * 1536;
        int tt = c >> 9, hh = (c >> 6) & 7, hss = c & 63;
        const float* bb = (tt == 0) ? bk : (tt == 1) ? bq : bv;
        g_Bqkv[idx] = bb[(ll * 8 + hh) * 64 + hss];
    }
}

__global__ void pack_rest_k(const float* __restrict__ Wp, const float* __restrict__ W1,
                            const float* __restrict__ W2, const float* __restrict__ Wlm) {
    int idx = blockIdx.x * 256 + threadIdx.x;          // < 2686976
    if (idx < 524288) {
        int l = idx >> 17, rem = idx & 131071;
        int n = rem >> 9, k = rem & 511;
        g_Wpt[idx] = tf32f(Wp[((size_t)l * 512 + k) * 256 + n]);
        return;
    }
    idx -= 524288;
    if (idx < 1048576) {
        int l = idx >> 18, rem = idx & 262143;
        int n = rem >> 8, d = rem & 255;
        g_W1t[idx] = tf32f(W1[((size_t)l * 256 + d) * 1024 + n]);
        return;
    }
    idx -= 1048576;
    if (idx < 1048576) {
        int l = idx >> 18, rem = idx & 262143;
        int n = rem >> 10, f = rem & 1023;
        g_W2t[idx] = tf32f(W2[((size_t)l * 1024 + f) * 256 + n]);
        return;
    }
    idx -= 1048576;
    if (idx < 65536) {
        int n = idx >> 8, d = idx & 255;
        g_Wlmt[idx] = tf32f(Wlm[d * 256 + n]);
    }
}

__global__ void mask_k(const int* __restrict__ dag) {
    int idx = blockIdx.x * 256 + threadIdx.x;          // < 524288
    int v = idx >> 18;
    int rem = idx & 262143;
    int i = rem >> 9;
    int j = rem & 511;
    unsigned char m = (dag[j * 512 + i] != 0 || (v && i == j)) ? 1 : 0;
    g_Amask[idx] = m;
    g_Amaskf[idx] = (float)m;
}

__global__ void xr_k(const float* __restrict__ X) {
    int i = blockIdx.x * 256 + threadIdx.x;            // < 2097152
    g_Xb[i] = tf32f(X[i]);
}

// ------------------------------- GEMM core ---------------------------------
struct GP {
    const float* A; const float* B; float* C;
    const float* bias; const float* res;
    float* dst0;
    int K, lda, ldb, ldc;
    long long sAz, sBz, sCz;
};

static const int GEMM_SMEM = 4 * (128 * 20 + 128 * 20) * 4;   // 81920 B

// MODE: 1 QKV scatter  3 AQ scatter  4 bias+swish(rounded)  5 bias+res(rounded)
//       6 bias(exact)  8 bias+swish dual (C exact, dst0 rounded)
template <int BN, int MODE>
__global__ __launch_bounds__(256) void gemm_tc(GP p) {
    constexpr int BM = 128, PITCH = 20, NS = 4;
    constexpr int WNW = (BN == 128) ? 4 : 2;
    constexpr int WM  = (BN == 128) ? 64 : 32;
    constexpr int WN  = 32;
    constexpr int MT = WM / 16, NT = WN / 8, NT2 = NT / 2;
    constexpr int ASZ = BM * PITCH, BSZ = BN * PITCH;

    extern __shared__ float dsm[];
    const unsigned sA = cvta_s(dsm);
    const unsigned sB = cvta_s(dsm + NS * ASZ);

    const int t = threadIdx.x, lane = t & 31, w = t >> 5;
    const int wm = w / WNW, wn = w % WNW;
    const int g = lane >> 2, cc = lane & 3;
    const int lrow = lane & 15;
    const unsigned loff = (unsigned)((lane >> 4) << 4);
    const int bx = blockIdx.x, by = blockIdx.y, bz = blockIdx.z;
    const int ar = t >> 2, ac = (t & 3) << 2;

    const float* Af = p.A + (size_t)bz * p.sAz + (size_t)by * BM * p.lda;
    const float* Bp = p.B + (size_t)bz * p.sBz + (size_t)bx * BN * p.ldb;
    float* C = p.C + (size_t)bz * p.sCz;

    float acc[MT][NT][4];
#pragma unroll
    for (int i = 0; i < MT; i++)
#pragma unroll
        for (int j = 0; j < NT; j++)
#pragma unroll
            for (int r = 0; r < 4; r++) acc[i][j][r] = 0.f;

    auto issue = [&](int ch, int s) {
        const int k0 = ch << 4;
        cpa16(sA + (unsigned)((s * ASZ + ar * PITCH + ac) * 4),
              Af + (size_t)ar * p.lda + k0 + ac);
        cpa16(sA + (unsigned)((s * ASZ + (ar + 64) * PITCH + ac) * 4),
              Af + (size_t)(ar + 64) * p.lda + k0 + ac);
        cpa16(sB + (unsigned)((s * BSZ + ar * PITCH + ac) * 4),
              Bp + (size_t)ar * p.ldb + k0 + ac);
        if (BN == 128)
            cpa16(sB + (unsigned)((s * BSZ + (ar + 64) * PITCH + ac) * 4),
                  Bp + (size_t)(ar + 64) * p.ldb + k0 + ac);
        CPA_COMMIT();
    };

    const int nch = p.K >> 4;
    issue(0, 0); issue(1, 1); issue(2, 2);
    for (int c = 0; c < nch; c++) {
        CPA_WAIT(2);
        __syncthreads();
        if (c + 3 < nch) issue(c + 3, (c + 3) & 3); else CPA_COMMIT();
        const int buf = c & 3;
#pragma unroll
        for (int ks = 0; ks < 2; ks++) {
            unsigned a[MT][4], b[NT][2];
#pragma unroll
            for (int i = 0; i < MT; i++) {
                const unsigned addr = sA + (unsigned)((buf * ASZ
                                    + (wm * WM + i * 16 + lrow) * PITCH + ks * 8) * 4) + loff;
                LDM_X4(a[i][0], a[i][1], a[i][2], a[i][3], addr);
            }
#pragma unroll
            for (int j2 = 0; j2 < NT2; j2++) {
                const unsigned addr = sB + (unsigned)((buf * BSZ
                                    + (wn * WN + j2 * 16 + lrow) * PITCH + ks * 8) * 4) + loff;
                LDM_X4(b[2 * j2][0], b[2 * j2 + 1][0], b[2 * j2][1], b[2 * j2 + 1][1], addr);
            }
#pragma unroll
            for (int i = 0; i < MT; i++)
#pragma unroll
                for (int j = 0; j < NT; j++)
                    MMA_TF32(acc[i][j], a[i], b[j]);
        }
    }

    // ------------------------------ epilogue -------------------------------
#pragma unroll
    for (int i = 0; i < MT; i++)
#pragma unroll
        for (int j = 0; j < NT; j++)
#pragma unroll
            for (int r = 0; r < 4; r++) {
                const int gm = by * BM + wm * WM + i * 16 + ((r >> 1) << 3) + g;
                const int gn = bx * BN + wn * WN + j * 8 + (cc << 1) + (r & 1);
                float v = acc[i][j][r];
                if (MODE == 1) {
                    v = swishf(v + p.bias[gn]);
                    const int tt = gn >> 9, h = (gn >> 6) & 7, hs = gn & 63;
                    const int b = gm >> 9, n = gm & 511, z = b * 8 + h;
                    if (tt == 0)      p.dst0[(size_t)(z * 512 + n) * 64 + hs] = tf32f(v);
                    else if (tt == 1) p.dst0[4194304u + (size_t)(z * 64 + hs) * 512 + n] = tf32f(v);
                    else              p.dst0[8388608u + (size_t)(z * 64 + hs) * 512 + n] = tf32f(v);
                } else if (MODE == 3) {
                    p.C[(size_t)(gn >> 6) * 32768 + (size_t)gm * 64 + (gn & 63)] = tf32f(v);
                } else if (MODE == 4) {
                    C[(size_t)gm * p.ldc + gn] = tf32f(swishf(v + p.bias[gn]));
                } else if (MODE == 5) {
                    C[(size_t)gm * p.ldc + gn] =
                        tf32f(v + p.bias[gn] + p.res[(size_t)gm * p.ldc + gn]);
                } else if (MODE == 6) {
                    C[(size_t)gm * p.ldc + gn] = v + p.bias[gn];
                } else {   // MODE 8: dual store
                    const float e = swishf(v + p.bias[gn]);
                    C[(size_t)gm * p.ldc + gn] = e;
                    p.dst0[(size_t)gm * p.ldc + gn] = tf32f(e);
                }
            }
}

// ------------------- fused attention: scores+softmax+PV --------------------
// Grid (8 i-tiles, 128 z).  smem floats: S 64x516 @0 | At 64x68 @33024 | Bt @37376
static const int ATTN_SMEM = (33024 + 4352 + 17408) * 4;   // 219136 B

__global__ __launch_bounds__(256) void attn_k(
    const float* __restrict__ AQ, const float* __restrict__ Kb,
    const float* __restrict__ Vt, const unsigned char* __restrict__ Mk,
    float* __restrict__ Ob) {
    extern __shared__ float sm[];
    float* S = sm;

    const int t = threadIdx.x, lane = t & 31, w = t >> 5;
    const int g = lane >> 2, cc = lane & 3;
    const int lrow = lane & 15;
    const unsigned loff = (unsigned)((lane >> 4) << 4);
    const int i0 = blockIdx.x * 64, z = blockIdx.y;

    const float* AQz = AQ + (size_t)z * 32768 + (size_t)i0 * 64;   // 64 x 64
    const float* Kp  = Kb + (size_t)z * 32768;                     // 512 x 64
    const float* Vz  = Vt + (size_t)z * 32768;                     // 64 x 512

    const unsigned sS = cvta_s(S);
    const unsigned sA = cvta_s(sm + 33024);
    const unsigned sB = cvta_s(sm + 37376);

    // ---- prologue: cp.async At (64x64 -> pitch 68) + K chunk 0 ------------
#pragma unroll
    for (int i = 0; i < 4; i++) {
        const int idx = i * 256 + t;
        const int r = idx >> 4, c = (idx & 15) << 2;
        cpa16(sA + (unsigned)((r * 68 + c) * 4), AQz + (size_t)r * 64 + c);
    }
    auto issueK = [&](int jc, int s) {
#pragma unroll
        for (int i = 0; i < 8; i++) {
            const int idx = i * 256 + t;
            const int r = idx >> 4, c = (idx & 15) << 2;
            cpa16(sB + (unsigned)((s * 8704 + r * 68 + c) * 4),
                  Kp + (size_t)(jc * 128 + r) * 64 + c);
        }
        CPA_COMMIT();
    };
    issueK(0, 0);   // single group: At + K0

    // ================= phase 1: S = AQ @ K^T, mask+scale ====================
    {
        const int wm = w >> 2, wn = w & 3;      // WM=32 (MT=2), WN=32 (NT=4)
        float acc[2][4][4];
        for (int jc = 0; jc < 4; jc++) {
            if (jc + 1 < 4) issueK(jc + 1, (jc + 1) & 1); else CPA_COMMIT();
            CPA_WAIT(1);
            __syncthreads();
#pragma unroll
            for (int i = 0; i < 2; i++)
#pragma unroll
                for (int j = 0; j < 4; j++)
#pragma unroll
                    for (int r = 0; r < 4; r++) acc[i][j][r] = 0.f;
            const int buf = jc & 1;
#pragma unroll
            for (int ks = 0; ks < 8; ks++) {
                unsigned a[2][4], b[4][2];
#pragma unroll
                for (int i = 0; i < 2; i++) {
                    const unsigned addr = sA + (unsigned)(((wm * 32 + i * 16 + lrow) * 68
                                        + ks * 8) * 4) + loff;
                    LDM_X4(a[i][0], a[i][1], a[i][2], a[i][3], addr);
                }
#pragma unroll
                for (int j2 = 0; j2 < 2; j2++) {
                    const unsigned addr = sB + (unsigned)((buf * 8704
                                        + (wn * 32 + j2 * 16 + lrow) * 68 + ks * 8) * 4) + loff;
                    LDM_X4(b[2 * j2][0], b[2 * j2 + 1][0], b[2 * j2][1], b[2 * j2 + 1][1], addr);
                }
#pragma unroll
                for (int i = 0; i < 2; i++)
#pragma unroll
                    for (int j = 0; j < 4; j++)
                        MMA_TF32(acc[i][j], a[i], b[j]);
            }
            // epilogue: mask+scale -> S
#pragma unroll
            for (int i = 0; i < 2; i++)
#pragma unroll
                for (int j = 0; j < 4; j++)
#pragma unroll
                    for (int r = 0; r < 4; r++) {
                        const int gm = wm * 32 + i * 16 + ((r >> 1) << 3) + g;
                        const int gn = jc * 128 + wn * 32 + j * 8 + (cc << 1) + (r & 1);
                        const float v = acc[i][j][r];
                        S[gm * 516 + gn] =
                            Mk[(size_t)(i0 + gm) * 512 + gn] ? v * 0.125f : -3.0e38f;
                    }
            __syncthreads();
        }
    }

    // ---- overlap: start V chunk 0 copy before softmax ----
    auto issueV = [&](int kc, int s) {
#pragma unroll
        for (int i = 0; i < 8; i++) {
            const int idx = i * 256 + t;
            const int r = idx >> 5, c = (idx & 31) << 2;
            cpa16(sB + (unsigned)((s * 8448 + r * 132 + c) * 4),
                  Vz + (size_t)r * 512 + kc * 128 + c);
        }
        CPA_COMMIT();
    };
    issueV(0, 0);

    // ================= phase 2: exact softmax + (P + A), tf32 ===============
    for (int it = 0; it < 8; it++) {
        const int ir = it * 8 + w;
        float* r = S + ir * 516;
        const unsigned char* mr = Mk + (size_t)(i0 + ir) * 512;
        float x[16];
        float m = -3.4e38f;
#pragma unroll
        for (int k = 0; k < 16; k++) { x[k] = r[k * 32 + lane]; m = fmaxf(m, x[k]); }
#pragma unroll
        for (int o = 16; o; o >>= 1) m = fmaxf(m, __shfl_xor_sync(0xffffffffu, m, o));
        if (m <= -1e37f) {
#pragma unroll
            for (int k = 0; k < 16; k++) r[k * 32 + lane] = 0.f;
        } else {
            float s = 0.f;
#pragma unroll
            for (int k = 0; k < 16; k++) { x[k] = __expf(x[k] - m); s += x[k]; }
#pragma unroll
            for (int o = 16; o; o >>= 1) s += __shfl_xor_sync(0xffffffffu, s, o);
            const float inv = 1.f / s;
#pragma unroll
            for (int k = 0; k < 16; k++)
                r[k * 32 + lane] = tf32f(x[k] * inv + (float)mr[k * 32 + lane]);
        }
    }
    __syncthreads();

    // ================= phase 3: O = Ssm @ V^T (4 x K=128 chunks) ============
    {
        const int wm = w >> 2, wn = w & 3;      // WM=32 (MT=2), WN=16 (NT=2)
        float oa[2][2][4];
#pragma unroll
        for (int i = 0; i < 2; i++)
#pragma unroll
            for (int j = 0; j < 2; j++)
#pragma unroll
                for (int r = 0; r < 4; r++) oa[i][j][r] = 0.f;
        for (int kc = 0; kc < 4; kc++) {
            if (kc + 1 < 4) issueV(kc + 1, (kc + 1) & 1); else CPA_COMMIT();
            CPA_WAIT(1);
            __syncthreads();
            const int buf = kc & 1;
#pragma unroll
            for (int ks = 0; ks < 16; ks++) {
                unsigned a[2][4], b[2][2];
#pragma unroll
                for (int i = 0; i < 2; i++) {
                    const unsigned addr = sS + (unsigned)(((wm * 32 + i * 16 + lrow) * 516
                                        + kc * 128 + ks * 8) * 4) + loff;
                    LDM_X4(a[i][0], a[i][1], a[i][2], a[i][3], addr);
                }
                {
                    const unsigned addr = sB + (unsigned)((buf * 8448
                                        + (wn * 16 + lrow) * 132 + ks * 8) * 4) + loff;
                    LDM_X4(b[0][0], b[1][0], b[0][1], b[1][1], addr);
                }
#pragma unroll
                for (int i = 0; i < 2; i++)
#pragma unroll
                    for (int j = 0; j < 2; j++)
                        MMA_TF32(oa[i][j], a[i], b[j]);
            }
            __syncthreads();
        }
        // epilogue -> Ob[(b*512 + i)][(h*64 + hs)]  (rounded: feeds proj GEMM)
        const int b = z >> 3, h = z & 7;
#pragma unroll
        for (int i = 0; i < 2; i++)
#pragma unroll
            for (int j = 0; j < 2; j++)
#pragma unroll
                for (int r = 0; r < 4; r++) {
                    const int gm = wm * 32 + i * 16 + ((r >> 1) << 3) + g;
                    const int gn = wn * 16 + j * 8 + (cc << 1) + (r & 1);
                    Ob[(size_t)(b * 512 + i0 + gm) * 512 + h * 64 + gn] = tf32f(oa[i][j][r]);
                }
    }
}

// ------------------------------ host driver --------------------------------
extern "C" void kernel_launch(void* const* d_in, const int* in_sizes, int n_in,
                              void* d_out, int out_size) {
    (void)in_sizes; (void)n_in; (void)out_size;
    const float* X   = (const float*)d_in[0];
    const int*   dag = (const int*)d_in[1];
    const float* Wk  = (const float*)d_in[2],  *bk  = (const float*)d_in[3];
    const float* Wq  = (const float*)d_in[4],  *bq  = (const float*)d_in[5];
    const float* Wv  = (const float*)d_in[6],  *bv  = (const float*)d_in[7];
    const float* Wp  = (const float*)d_in[8],  *bp  = (const float*)d_in[9];
    const float* W1  = (const float*)d_in[10], *b1  = (const float*)d_in[11];
    const float* W2  = (const float*)d_in[12], *b2  = (const float*)d_in[13];
    const float* Wlm = (const float*)d_in[14], *blm = (const float*)d_in[15];
    float* out = (float*)d_out;

    cudaFuncSetAttribute(gemm_tc<128, 1>, cudaFuncAttributeMaxDynamicSharedMemorySize, GEMM_SMEM);
    cudaFuncSetAttribute(gemm_tc<128, 3>, cudaFuncAttributeMaxDynamicSharedMemorySize, GEMM_SMEM);
    cudaFuncSetAttribute(gemm_tc<128, 4>, cudaFuncAttributeMaxDynamicSharedMemorySize, GEMM_SMEM);
    cudaFuncSetAttribute(gemm_tc<128, 5>, cudaFuncAttributeMaxDynamicSharedMemorySize, GEMM_SMEM);
    cudaFuncSetAttribute(gemm_tc<128, 6>, cudaFuncAttributeMaxDynamicSharedMemorySize, GEMM_SMEM);
    cudaFuncSetAttribute(gemm_tc<128, 8>, cudaFuncAttributeMaxDynamicSharedMemorySize, GEMM_SMEM);
    cudaFuncSetAttribute(attn_k, cudaFuncAttributeMaxDynamicSharedMemorySize, ATTN_SMEM);

    void* pv;
    cudaGetSymbolAddress(&pv, g_Wqkvt); float* Wqkvt = (float*)pv;
    cudaGetSymbolAddress(&pv, g_Bqkv);  float* Bqkv  = (float*)pv;
    cudaGetSymbolAddress(&pv, g_Wpt);   float* Wpt   = (float*)pv;
    cudaGetSymbolAddress(&pv, g_W1t);   float* W1t   = (float*)pv;
    cudaGetSymbolAddress(&pv, g_W2t);   float* W2t   = (float*)pv;
    cudaGetSymbolAddress(&pv, g_Wlmt);  float* Wlmt  = (float*)pv;
    cudaGetSymbolAddress(&pv, g_Amask); unsigned char* Amask = (unsigned char*)pv;
    cudaGetSymbolAddress(&pv, g_Amaskf); float* Amaskf = (float*)pv;
    cudaGetSymbolAddress(&pv, g_KQV);   float* KQV = (float*)pv;
    cudaGetSymbolAddress(&pv, g_AQ4);   float* AQ4 = (float*)pv;
    cudaGetSymbolAddress(&pv, g_Ob);    float* Ob  = (float*)pv;
    cudaGetSymbolAddress(&pv, g_Mha);   float* Mha = (float*)pv;
    cudaGetSymbolAddress(&pv, g_Mhar);  float* Mhar = (float*)pv;
    cudaGetSymbolAddress(&pv, g_Ff);    float* Ff  = (float*)pv;
    cudaGetSymbolAddress(&pv, g_Xb);    float* Xb  = (float*)pv;

    pack_qkv_k<<<6144, 256>>>(Wk, Wq, Wv, bk, bq, bv);
    pack_rest_k<<<10496, 256>>>(Wp, W1, W2, Wlm);
    mask_k<<<2048, 256>>>(dag);
    xr_k<<<8192, 256>>>(X);

    for (int l = 0; l < 4; l++) {
        const unsigned char* Am = Amask + (l ? 262144 : 0);
        const float* Amf = Amaskf + (l ? 262144 : 0);
        {   // QKV: Xb @ Wqkvt^T -> scatter K/Qt/Vt (+bias+swish, rounded)
            GP p{}; p.A = Xb; p.lda = 256;
            p.B = Wqkvt + (size_t)l * 1536 * 256; p.ldb = 256;
            p.bias = Bqkv + l * 1536; p.dst0 = KQV; p.K = 256;
            gemm_tc<128, 1><<<dim3(12, 64, 1), 256, GEMM_SMEM>>>(p);
        }
        {   // AQ = maskf @ Qt^T -> AQ4[z][i][hs]  (rounded)
            GP p{}; p.A = Amf; p.lda = 512;
            p.B = KQV + 4194304; p.ldb = 512;
            p.C = AQ4; p.K = 512;
            gemm_tc<128, 3><<<dim3(64, 4, 1), 256, GEMM_SMEM>>>(p);
        }
        attn_k<<<dim3(8, 128), 256, ATTN_SMEM>>>(AQ4, KQV, KQV + 2 * 4194304, Am, Ob);
        {   // mha = swish(Ob @ Wpt^T + bp): Mha exact + Mhar rounded
            GP p{}; p.A = Ob; p.lda = 512;
            p.B = Wpt + (size_t)l * 256 * 512; p.ldb = 512;
            p.bias = bp + l * 256; p.C = Mha; p.ldc = 256; p.dst0 = Mhar; p.K = 512;
            gemm_tc<128, 8><<<dim3(2, 64, 1), 256, GEMM_SMEM>>>(p);
        }
        {   // ff = swish(Mhar @ W1t^T + b1)  (rounded)
            GP p{}; p.A = Mhar; p.lda = 256;
            p.B = W1t + (size_t)l * 1024 * 256; p.ldb = 256;
            p.bias = b1 + l * 1024; p.C = Ff; p.ldc = 1024; p.K = 256;
            gemm_tc<128, 4><<<dim3(8, 64, 1), 256, GEMM_SMEM>>>(p);
        }
        {   // Xb = Ff @ W2t^T + b2 + Mha  (rounded: feeds next QKV / lm)
            GP p{}; p.A = Ff; p.lda = 1024;
            p.B = W2t + (size_t)l * 256 * 1024; p.ldb = 1024;
            p.bias = b2 + l * 256; p.res = Mha; p.C = Xb; p.ldc = 256; p.K = 1024;
            gemm_tc<128, 5><<<dim3(2, 64, 1), 256, GEMM_SMEM>>>(p);
        }
    }
    {   // lm head (exact output)
        GP p{}; p.A = Xb; p.lda = 256; p.B = Wlmt; p.ldb = 256;
        p.bias = blm; p.C = out; p.ldc = 256; p.K = 256;
        gemm_tc<128, 6><<<dim3(2, 64, 1), 256, GEMM_SMEM>>>(p);
    }
}

// round 10
// speedup vs baseline: 2.6657x; 1.0795x over previous
#include <cuda_runtime.h>
#include <cstdint>

// ---------------------------------------------------------------------------
// CaT transformer, tf32 mma.sync (portable sm_100 target).
// R10: 2 CTAs/SM on all GEMMs (launch_bounds(256,2)); attention kernel at
// 512 threads; BN=64 tiles for small-grid GEMMs. Numerics bit-identical
// to R9 (oracle rel_err 7.903782e-4).
// ---------------------------------------------------------------------------

#define DI __device__ __forceinline__

static DI float swishf(float x) { return x / (1.f + __expf(-x)); }

// ------------------------- static device scratch ---------------------------
__device__ float g_Wqkvt[4 * 1536 * 256];   // tf32
__device__ float g_Bqkv [4 * 1536];
__device__ float g_Wpt  [4 * 256 * 512];    // tf32
__device__ float g_W1t  [4 * 1024 * 256];   // tf32
__device__ float g_W2t  [4 * 256 * 1024];   // tf32
__device__ float g_Wlmt [256 * 256];        // tf32
__device__ unsigned char g_Amask[2 * 512 * 512];
__device__ float g_Amaskf[2 * 512 * 512];   // 0.0 / 1.0
__device__ float g_KQV[3 * 512 * 8192];     // K | Qt | Vt (tf32)
__device__ float g_AQ4[512 * 8192];         // tf32
__device__ float g_Ob [8192 * 512];         // tf32
__device__ float g_Mha[8192 * 256];         // exact residual
__device__ float g_Mhar[8192 * 256];        // tf32
__device__ float g_Ff [8192 * 1024];        // tf32
__device__ float g_Xb [8192 * 256];         // tf32

// --------------------------- helpers ---------------------------------------
DI unsigned tf32_rn(float x) {
    unsigned r;
    asm("cvt.rn.tf32.f32 %0, %1;" : "=r"(r) : "f"(x));
    return r;
}
DI float tf32f(float x) { return __uint_as_float(tf32_rn(x)); }
DI unsigned cvta_s(const void* p) { return (unsigned)__cvta_generic_to_shared(p); }
DI void cpa16(unsigned dst, const void* src) {
    asm volatile("cp.async.cg.shared.global [%0], [%1], 16;" :: "r"(dst), "l"(src) : "memory");
}
#define CPA_COMMIT() asm volatile("cp.async.commit_group;" ::: "memory")
#define CPA_WAIT(N)  asm volatile("cp.async.wait_group %0;" :: "n"(N) : "memory")

#define LDM_X4(r0, r1, r2, r3, addr) \
    asm volatile("ldmatrix.sync.aligned.m8n8.x4.shared.b16 {%0,%1,%2,%3}, [%4];" \
                 : "=r"(r0), "=r"(r1), "=r"(r2), "=r"(r3) : "r"(addr))
#define MMA_TF32(d, a, b) \
    asm volatile("mma.sync.aligned.m16n8k8.row.col.f32.tf32.tf32.f32 " \
                 "{%0,%1,%2,%3}, {%4,%5,%6,%7}, {%8,%9}, {%0,%1,%2,%3};" \
                 : "+f"((d)[0]), "+f"((d)[1]), "+f"((d)[2]), "+f"((d)[3]) \
                 : "r"((a)[0]), "r"((a)[1]), "r"((a)[2]), "r"((a)[3]), \
                   "r"((b)[0]), "r"((b)[1]))

// ------------------------------ prep kernels -------------------------------
__global__ void pack_qkv_k(const float* __restrict__ Wk, const float* __restrict__ Wq,
                           const float* __restrict__ Wv, const float* __restrict__ bk,
                           const float* __restrict__ bq, const float* __restrict__ bv) {
    int idx = blockIdx.x * 256 + threadIdx.x;          // < 1572864
    int l = idx / 393216;
    int rem = idx - l * 393216;
    int r = rem >> 8;
    int d = rem & 255;
    int t = r >> 9, h = (r >> 6) & 7, hs = r & 63;
    const float* W = (t == 0) ? Wk : (t == 1) ? Wq : Wv;
    g_Wqkvt[idx] = tf32f(W[(((size_t)(l * 8 + h)) * 256 + d) * 64 + hs]);
    if (idx < 4 * 1536) {
        int ll = idx / 1536;
        int c = idx - ll * 1536;
        int tt = c >> 9, hh = (c >> 6) & 7, hss = c & 63;
        const float* bb = (tt == 0) ? bk : (tt == 1) ? bq : bv;
        g_Bqkv[idx] = bb[(ll * 8 + hh) * 64 + hss];
    }
}

__global__ void pack_rest_k(const float* __restrict__ Wp, const float* __restrict__ W1,
                            const float* __restrict__ W2, const float* __restrict__ Wlm) {
    int idx = blockIdx.x * 256 + threadIdx.x;          // < 2686976
    if (idx < 524288) {
        int l = idx >> 17, rem = idx & 131071;
        int n = rem >> 9, k = rem & 511;
        g_Wpt[idx] = tf32f(Wp[((size_t)l * 512 + k) * 256 + n]);
        return;
    }
    idx -= 524288;
    if (idx < 1048576) {
        int l = idx >> 18, rem = idx & 262143;
        int n = rem >> 8, d = rem & 255;
        g_W1t[idx] = tf32f(W1[((size_t)l * 256 + d) * 1024 + n]);
        return;
    }
    idx -= 1048576;
    if (idx < 1048576) {
        int l = idx >> 18, rem = idx & 262143;
        int n = rem >> 10, f = rem & 1023;
        g_W2t[idx] = tf32f(W2[((size_t)l * 1024 + f) * 256 + n]);
        return;
    }
    idx -= 1048576;
    if (idx < 65536) {
        int n = idx >> 8, d = idx & 255;
        g_Wlmt[idx] = tf32f(Wlm[d * 256 + n]);
    }
}

__global__ void mask_k(const int* __restrict__ dag) {
    int idx = blockIdx.x * 256 + threadIdx.x;          // < 524288
    int v = idx >> 18;
    int rem = idx & 262143;
    int i = rem >> 9;
    int j = rem & 511;
    unsigned char m = (dag[j * 512 + i] != 0 || (v && i == j)) ? 1 : 0;
    g_Amask[idx] = m;
    g_Amaskf[idx] = (float)m;
}

__global__ void xr_k(const float* __restrict__ X) {
    int i = blockIdx.x * 256 + threadIdx.x;            // < 2097152
    g_Xb[i] = tf32f(X[i]);
}

// ------------------------------- GEMM core ---------------------------------
struct GP {
    const float* A; const float* B; float* C;
    const float* bias; const float* res;
    float* dst0;
    int K, lda, ldb, ldc;
    long long sAz, sBz, sCz;
};

static const int GEMM_SMEM128 = 4 * (128 * 20 + 128 * 20) * 4;   // 81920 B
static const int GEMM_SMEM64  = 4 * (128 * 20 +  64 * 20) * 4;   // 61440 B

// MODE: 1 QKV scatter  3 AQ scatter  4 bias+swish(rounded)  5 bias+res(rounded)
//       6 bias(exact)  8 bias+swish dual (C exact, dst0 rounded)
template <int BN, int MODE>
__global__ __launch_bounds__(256, 2) void gemm_tc(GP p) {
    constexpr int BM = 128, PITCH = 20, NS = 4;
    constexpr int WNW = (BN == 128) ? 4 : 2;
    constexpr int WM  = (BN == 128) ? 64 : 32;
    constexpr int WN  = 32;
    constexpr int MT = WM / 16, NT = WN / 8, NT2 = NT / 2;
    constexpr int ASZ = BM * PITCH, BSZ = BN * PITCH;

    extern __shared__ float dsm[];
    const unsigned sA = cvta_s(dsm);
    const unsigned sB = cvta_s(dsm + NS * ASZ);

    const int t = threadIdx.x, lane = t & 31, w = t >> 5;
    const int wm = w / WNW, wn = w % WNW;
    const int g = lane >> 2, cc = lane & 3;
    const int lrow = lane & 15;
    const unsigned loff = (unsigned)((lane >> 4) << 4);
    const int bx = blockIdx.x, by = blockIdx.y, bz = blockIdx.z;
    const int ar = t >> 2, ac = (t & 3) << 2;

    const float* Af = p.A + (size_t)bz * p.sAz + (size_t)by * BM * p.lda;
    const float* Bp = p.B + (size_t)bz * p.sBz + (size_t)bx * BN * p.ldb;
    float* C = p.C + (size_t)bz * p.sCz;

    float acc[MT][NT][4];
#pragma unroll
    for (int i = 0; i < MT; i++)
#pragma unroll
        for (int j = 0; j < NT; j++)
#pragma unroll
            for (int r = 0; r < 4; r++) acc[i][j][r] = 0.f;

    auto issue = [&](int ch, int s) {
        const int k0 = ch << 4;
        cpa16(sA + (unsigned)((s * ASZ + ar * PITCH + ac) * 4),
              Af + (size_t)ar * p.lda + k0 + ac);
        cpa16(sA + (unsigned)((s * ASZ + (ar + 64) * PITCH + ac) * 4),
              Af + (size_t)(ar + 64) * p.lda + k0 + ac);
        cpa16(sB + (unsigned)((s * BSZ + ar * PITCH + ac) * 4),
              Bp + (size_t)ar * p.ldb + k0 + ac);
        if (BN == 128)
            cpa16(sB + (unsigned)((s * BSZ + (ar + 64) * PITCH + ac) * 4),
                  Bp + (size_t)(ar + 64) * p.ldb + k0 + ac);
        CPA_COMMIT();
    };

    const int nch = p.K >> 4;
    issue(0, 0); issue(1, 1); issue(2, 2);
    for (int c = 0; c < nch; c++) {
        CPA_WAIT(2);
        __syncthreads();
        if (c + 3 < nch) issue(c + 3, (c + 3) & 3); else CPA_COMMIT();
        const int buf = c & 3;
#pragma unroll
        for (int ks = 0; ks < 2; ks++) {
            unsigned a[MT][4], b[NT][2];
#pragma unroll
            for (int i = 0; i < MT; i++) {
                const unsigned addr = sA + (unsigned)((buf * ASZ
                                    + (wm * WM + i * 16 + lrow) * PITCH + ks * 8) * 4) + loff;
                LDM_X4(a[i][0], a[i][1], a[i][2], a[i][3], addr);
            }
#pragma unroll
            for (int j2 = 0; j2 < NT2; j2++) {
                const unsigned addr = sB + (unsigned)((buf * BSZ
                                    + (wn * WN + j2 * 16 + lrow) * PITCH + ks * 8) * 4) + loff;
                LDM_X4(b[2 * j2][0], b[2 * j2 + 1][0], b[2 * j2][1], b[2 * j2 + 1][1], addr);
            }
#pragma unroll
            for (int i = 0; i < MT; i++)
#pragma unroll
                for (int j = 0; j < NT; j++)
                    MMA_TF32(acc[i][j], a[i], b[j]);
        }
    }

    // ------------------------------ epilogue -------------------------------
#pragma unroll
    for (int i = 0; i < MT; i++)
#pragma unroll
        for (int j = 0; j < NT; j++)
#pragma unroll
            for (int r = 0; r < 4; r++) {
                const int gm = by * BM + wm * WM + i * 16 + ((r >> 1) << 3) + g;
                const int gn = bx * BN + wn * WN + j * 8 + (cc << 1) + (r & 1);
                float v = acc[i][j][r];
                if (MODE == 1) {
                    v = swishf(v + p.bias[gn]);
                    const int tt = gn >> 9, h = (gn >> 6) & 7, hs = gn & 63;
                    const int b = gm >> 9, n = gm & 511, z = b * 8 + h;
                    if (tt == 0)      p.dst0[(size_t)(z * 512 + n) * 64 + hs] = tf32f(v);
                    else if (tt == 1) p.dst0[4194304u + (size_t)(z * 64 + hs) * 512 + n] = tf32f(v);
                    else              p.dst0[8388608u + (size_t)(z * 64 + hs) * 512 + n] = tf32f(v);
                } else if (MODE == 3) {
                    p.C[(size_t)(gn >> 6) * 32768 + (size_t)gm * 64 + (gn & 63)] = tf32f(v);
                } else if (MODE == 4) {
                    C[(size_t)gm * p.ldc + gn] = tf32f(swishf(v + p.bias[gn]));
                } else if (MODE == 5) {
                    C[(size_t)gm * p.ldc + gn] =
                        tf32f(v + p.bias[gn] + p.res[(size_t)gm * p.ldc + gn]);
                } else if (MODE == 6) {
                    C[(size_t)gm * p.ldc + gn] = v + p.bias[gn];
                } else {   // MODE 8
                    const float e = swishf(v + p.bias[gn]);
                    C[(size_t)gm * p.ldc + gn] = e;
                    p.dst0[(size_t)gm * p.ldc + gn] = tf32f(e);
                }
            }
}

// ------------------- fused attention: scores+softmax+PV --------------------
// Grid (8 i-tiles, 128 z), 512 threads (16 warps).
// smem floats: S 64x516 @0 | At 64x68 @33024 | Bt @37376
static const int ATTN_SMEM = (33024 + 4352 + 17408) * 4;   // 219136 B

__global__ __launch_bounds__(512) void attn_k(
    const float* __restrict__ AQ, const float* __restrict__ Kb,
    const float* __restrict__ Vt, const unsigned char* __restrict__ Mk,
    float* __restrict__ Ob) {
    extern __shared__ float sm[];
    float* S = sm;

    const int t = threadIdx.x, lane = t & 31, w = t >> 5;     // w: 0..15
    const int g = lane >> 2, cc = lane & 3;
    const int lrow = lane & 15;
    const unsigned loff = (unsigned)((lane >> 4) << 4);
    const int i0 = blockIdx.x * 64, z = blockIdx.y;

    const float* AQz = AQ + (size_t)z * 32768 + (size_t)i0 * 64;   // 64 x 64
    const float* Kp  = Kb + (size_t)z * 32768;                     // 512 x 64
    const float* Vz  = Vt + (size_t)z * 32768;                     // 64 x 512

    const unsigned sS = cvta_s(S);
    const unsigned sA = cvta_s(sm + 33024);
    const unsigned sB = cvta_s(sm + 37376);

    // ---- prologue: cp.async At (64x64 -> pitch 68) + K chunk 0 ------------
#pragma unroll
    for (int i = 0; i < 2; i++) {
        const int idx = i * 512 + t;
        const int r = idx >> 4, c = (idx & 15) << 2;
        cpa16(sA + (unsigned)((r * 68 + c) * 4), AQz + (size_t)r * 64 + c);
    }
    auto issueK = [&](int jc, int s) {
#pragma unroll
        for (int i = 0; i < 4; i++) {
            const int idx = i * 512 + t;
            const int r = idx >> 4, c = (idx & 15) << 2;
            cpa16(sB + (unsigned)((s * 8704 + r * 68 + c) * 4),
                  Kp + (size_t)(jc * 128 + r) * 64 + c);
        }
        CPA_COMMIT();
    };
    issueK(0, 0);   // single group: At + K0

    // ================= phase 1: S = AQ @ K^T, mask+scale ====================
    {
        const int wm = w >> 2, wn = w & 3;      // 4x4 warps: 16 rows x 32 cols
        float acc[4][4];
        for (int jc = 0; jc < 4; jc++) {
            if (jc + 1 < 4) issueK(jc + 1, (jc + 1) & 1); else CPA_COMMIT();
            CPA_WAIT(1);
            __syncthreads();
#pragma unroll
            for (int j = 0; j < 4; j++)
#pragma unroll
                for (int r = 0; r < 4; r++) acc[j][r] = 0.f;
            const int buf = jc & 1;
#pragma unroll
            for (int ks = 0; ks < 8; ks++) {
                unsigned a[4], b[4][2];
                {
                    const unsigned addr = sA + (unsigned)(((wm * 16 + lrow) * 68
                                        + ks * 8) * 4) + loff;
                    LDM_X4(a[0], a[1], a[2], a[3], addr);
                }
#pragma unroll
                for (int j2 = 0; j2 < 2; j2++) {
                    const unsigned addr = sB + (unsigned)((buf * 8704
                                        + (wn * 32 + j2 * 16 + lrow) * 68 + ks * 8) * 4) + loff;
                    LDM_X4(b[2 * j2][0], b[2 * j2 + 1][0], b[2 * j2][1], b[2 * j2 + 1][1], addr);
                }
#pragma unroll
                for (int j = 0; j < 4; j++)
                    MMA_TF32(acc[j], a, b[j]);
            }
            // epilogue: mask+scale -> S
#pragma unroll
            for (int j = 0; j < 4; j++)
#pragma unroll
                for (int r = 0; r < 4; r++) {
                    const int gm = wm * 16 + ((r >> 1) << 3) + g;
                    const int gn = jc * 128 + wn * 32 + j * 8 + (cc << 1) + (r & 1);
                    const float v = acc[j][r];
                    S[gm * 516 + gn] =
                        Mk[(size_t)(i0 + gm) * 512 + gn] ? v * 0.125f : -3.0e38f;
                }
            __syncthreads();
        }
    }

    // ---- overlap: start V chunk 0 copy before softmax ----
    auto issueV = [&](int kc, int s) {
#pragma unroll
        for (int i = 0; i < 4; i++) {
            const int idx = i * 512 + t;
            const int r = idx >> 5, c = (idx & 31) << 2;
            cpa16(sB + (unsigned)((s * 8448 + r * 132 + c) * 4),
                  Vz + (size_t)r * 512 + kc * 128 + c);
        }
        CPA_COMMIT();
    };
    issueV(0, 0);

    // ================= phase 2: exact softmax + (P + A), tf32 ===============
    for (int it = 0; it < 4; it++) {
        const int ir = it * 16 + w;
        float* r = S + ir * 516;
        const unsigned char* mr = Mk + (size_t)(i0 + ir) * 512;
        float x[16];
        float m = -3.4e38f;
#pragma unroll
        for (int k = 0; k < 16; k++) { x[k] = r[k * 32 + lane]; m = fmaxf(m, x[k]); }
#pragma unroll
        for (int o = 16; o; o >>= 1) m = fmaxf(m, __shfl_xor_sync(0xffffffffu, m, o));
        if (m <= -1e37f) {
#pragma unroll
            for (int k = 0; k < 16; k++) r[k * 32 + lane] = 0.f;
        } else {
            float s = 0.f;
#pragma unroll
            for (int k = 0; k < 16; k++) { x[k] = __expf(x[k] - m); s += x[k]; }
#pragma unroll
            for (int o = 16; o; o >>= 1) s += __shfl_xor_sync(0xffffffffu, s, o);
            const float inv = 1.f / s;
#pragma unroll
            for (int k = 0; k < 16; k++)
                r[k * 32 + lane] = tf32f(x[k] * inv + (float)mr[k * 32 + lane]);
        }
    }
    __syncthreads();

    // ================= phase 3: O = Ssm @ V^T (4 x K=128 chunks) ============
    {
        const int wm = w >> 2, wn = w & 3;      // 4x4 warps: 16 rows x 16 cols
        float oa[2][4];
#pragma unroll
        for (int j = 0; j < 2; j++)
#pragma unroll
            for (int r = 0; r < 4; r++) oa[j][r] = 0.f;
        for (int kc = 0; kc < 4; kc++) {
            if (kc + 1 < 4) issueV(kc + 1, (kc + 1) & 1); else CPA_COMMIT();
            CPA_WAIT(1);
            __syncthreads();
            const int buf = kc & 1;
#pragma unroll
            for (int ks = 0; ks < 16; ks++) {
                unsigned a[4], b[2][2];
                {
                    const unsigned addr = sS + (unsigned)(((wm * 16 + lrow) * 516
                                        + kc * 128 + ks * 8) * 4) + loff;
                    LDM_X4(a[0], a[1], a[2], a[3], addr);
                }
                {
                    const unsigned addr = sB + (unsigned)((buf * 8448
                                        + (wn * 16 + lrow) * 132 + ks * 8) * 4) + loff;
                    LDM_X4(b[0][0], b[1][0], b[0][1], b[1][1], addr);
                }
#pragma unroll
                for (int j = 0; j < 2; j++)
                    MMA_TF32(oa[j], a, b[j]);
            }
            __syncthreads();
        }
        // epilogue -> Ob[(b*512 + i)][(h*64 + hs)]  (rounded)
        const int b = z >> 3, h = z & 7;
#pragma unroll
        for (int j = 0; j < 2; j++)
#pragma unroll
            for (int r = 0; r < 4; r++) {
                const int gm = wm * 16 + ((r >> 1) << 3) + g;
                const int gn = wn * 16 + j * 8 + (cc << 1) + (r & 1);
                Ob[(size_t)(b * 512 + i0 + gm) * 512 + h * 64 + gn] = tf32f(oa[j][r]);
            }
    }
}

// ------------------------------ host driver --------------------------------
extern "C" void kernel_launch(void* const* d_in, const int* in_sizes, int n_in,
                              void* d_out, int out_size) {
    (void)in_sizes; (void)n_in; (void)out_size;
    const float* X   = (const float*)d_in[0];
    const int*   dag = (const int*)d_in[1];
    const float* Wk  = (const float*)d_in[2],  *bk  = (const float*)d_in[3];
    const float* Wq  = (const float*)d_in[4],  *bq  = (const float*)d_in[5];
    const float* Wv  = (const float*)d_in[6],  *bv  = (const float*)d_in[7];
    const float* Wp  = (const float*)d_in[8],  *bp  = (const float*)d_in[9];
    const float* W1  = (const float*)d_in[10], *b1  = (const float*)d_in[11];
    const float* W2  = (const float*)d_in[12], *b2  = (const float*)d_in[13];
    const float* Wlm = (const float*)d_in[14], *blm = (const float*)d_in[15];
    float* out = (float*)d_out;

    cudaFuncSetAttribute(gemm_tc<128, 1>, cudaFuncAttributeMaxDynamicSharedMemorySize, GEMM_SMEM128);
    cudaFuncSetAttribute(gemm_tc<128, 3>, cudaFuncAttributeMaxDynamicSharedMemorySize, GEMM_SMEM128);
    cudaFuncSetAttribute(gemm_tc<128, 4>, cudaFuncAttributeMaxDynamicSharedMemorySize, GEMM_SMEM128);
    cudaFuncSetAttribute(gemm_tc<64, 8>,  cudaFuncAttributeMaxDynamicSharedMemorySize, GEMM_SMEM64);
    cudaFuncSetAttribute(gemm_tc<64, 5>,  cudaFuncAttributeMaxDynamicSharedMemorySize, GEMM_SMEM64);
    cudaFuncSetAttribute(gemm_tc<64, 6>,  cudaFuncAttributeMaxDynamicSharedMemorySize, GEMM_SMEM64);
    cudaFuncSetAttribute(attn_k, cudaFuncAttributeMaxDynamicSharedMemorySize, ATTN_SMEM);

    void* pv;
    cudaGetSymbolAddress(&pv, g_Wqkvt); float* Wqkvt = (float*)pv;
    cudaGetSymbolAddress(&pv, g_Bqkv);  float* Bqkv  = (float*)pv;
    cudaGetSymbolAddress(&pv, g_Wpt);   float* Wpt   = (float*)pv;
    cudaGetSymbolAddress(&pv, g_W1t);   float* W1t   = (float*)pv;
    cudaGetSymbolAddress(&pv, g_W2t);   float* W2t   = (float*)pv;
    cudaGetSymbolAddress(&pv, g_Wlmt);  float* Wlmt  = (float*)pv;
    cudaGetSymbolAddress(&pv, g_Amask); unsigned char* Amask = (unsigned char*)pv;
    cudaGetSymbolAddress(&pv, g_Amaskf); float* Amaskf = (float*)pv;
    cudaGetSymbolAddress(&pv, g_KQV);   float* KQV = (float*)pv;
    cudaGetSymbolAddress(&pv, g_AQ4);   float* AQ4 = (float*)pv;
    cudaGetSymbolAddress(&pv, g_Ob);    float* Ob  = (float*)pv;
    cudaGetSymbolAddress(&pv, g_Mha);   float* Mha = (float*)pv;
    cudaGetSymbolAddress(&pv, g_Mhar);  float* Mhar = (float*)pv;
    cudaGetSymbolAddress(&pv, g_Ff);    float* Ff  = (float*)pv;
    cudaGetSymbolAddress(&pv, g_Xb);    float* Xb  = (float*)pv;

    pack_qkv_k<<<6144, 256>>>(Wk, Wq, Wv, bk, bq, bv);
    pack_rest_k<<<10496, 256>>>(Wp, W1, W2, Wlm);
    mask_k<<<2048, 256>>>(dag);
    xr_k<<<8192, 256>>>(X);

    for (int l = 0; l < 4; l++) {
        const unsigned char* Am = Amask + (l ? 262144 : 0);
        const float* Amf = Amaskf + (l ? 262144 : 0);
        {   // QKV: Xb @ Wqkvt^T -> scatter K/Qt/Vt (+bias+swish, rounded)
            GP p{}; p.A = Xb; p.lda = 256;
            p.B = Wqkvt + (size_t)l * 1536 * 256; p.ldb = 256;
            p.bias = Bqkv + l * 1536; p.dst0 = KQV; p.K = 256;
            gemm_tc<128, 1><<<dim3(12, 64, 1), 256, GEMM_SMEM128>>>(p);
        }
        {   // AQ = maskf @ Qt^T -> AQ4[z][i][hs]  (rounded)
            GP p{}; p.A = Amf; p.lda = 512;
            p.B = KQV + 4194304; p.ldb = 512;
            p.C = AQ4; p.K = 512;
            gemm_tc<128, 3><<<dim3(64, 4, 1), 256, GEMM_SMEM128>>>(p);
        }
        attn_k<<<dim3(8, 128), 512, ATTN_SMEM>>>(AQ4, KQV, KQV + 2 * 4194304, Am, Ob);
        {   // mha = swish(Ob @ Wpt^T + bp): Mha exact + Mhar rounded
            GP p{}; p.A = Ob; p.lda = 512;
            p.B = Wpt + (size_t)l * 256 * 512; p.ldb = 512;
            p.bias = bp + l * 256; p.C = Mha; p.ldc = 256; p.dst0 = Mhar; p.K = 512;
            gemm_tc<64, 8><<<dim3(4, 64, 1), 256, GEMM_SMEM64>>>(p);
        }
        {   // ff = swish(Mhar @ W1t^T + b1)  (rounded)
            GP p{}; p.A = Mhar; p.lda = 256;
            p.B = W1t + (size_t)l * 1024 * 256; p.ldb = 256;
            p.bias = b1 + l * 1024; p.C = Ff; p.ldc = 1024; p.K = 256;
            gemm_tc<128, 4><<<dim3(8, 64, 1), 256, GEMM_SMEM128>>>(p);
        }
        {   // Xb = Ff @ W2t^T + b2 + Mha  (rounded)
            GP p{}; p.A = Ff; p.lda = 1024;
            p.B = W2t + (size_t)l * 256 * 1024; p.ldb = 1024;
            p.bias = b2 + l * 256; p.res = Mha; p.C = Xb; p.ldc = 256; p.K = 1024;
            gemm_tc<64, 5><<<dim3(4, 64, 1), 256, GEMM_SMEM64>>>(p);
        }
    }
    {   // lm head (exact output)
        GP p{}; p.A = Xb; p.lda = 256; p.B = Wlmt; p.ldb = 256;
        p.bias = blm; p.C = out; p.ldc = 256; p.K = 256;
        gemm_tc<64, 6><<<dim3(4, 64, 1), 256, GEMM_SMEM64>>>(p);
    }
}